// round 1
// baseline (speedup 1.0000x reference)
#include <cuda_runtime.h>
#include <math.h>

#define HIDDEN 2048
#define NHEADS 16
#define NKV 4
#define HD 128
#define SEQ 2048
#define BATCH 2
#define MROWS (BATCH * SEQ)   // 4096
#define KVW (NKV * HD)        // 512
#define QSCALE 0.08838834764831845f  // 1/sqrt(128)

// ---------------- scratch (no allocations allowed) ----------------
__device__ __align__(128) float g_q[MROWS * HIDDEN];
__device__ __align__(128) float g_k[MROWS * KVW];
__device__ __align__(128) float g_v[MROWS * KVW];
__device__ __align__(128) float g_att[MROWS * HIDDEN];

// ---------------- SGEMM: C[M,N] = A[M,K] @ B[K,N], all row-major ----------------
// 128x128 block tile, BK=8, 256 threads, 8x8 micro-tile per thread.
// Requires: M,N multiples of 128; K multiple of 8.
__global__ __launch_bounds__(256, 2)
void sgemm128(const float* __restrict__ A, const float* __restrict__ B,
              float* __restrict__ C, int N, int K)
{
    __shared__ float As[8][132];  // staged transposed: As[k][m]
    __shared__ float Bs[8][132];  // Bs[k][n]

    const int tid = threadIdx.x;
    const int tx = tid & 15;
    const int ty = tid >> 4;
    const int m0 = blockIdx.y << 7;
    const int n0 = blockIdx.x << 7;

    // A tile load: 128 rows x 8 cols; each thread: one float4
    const int arow = tid >> 1;
    const int acol = (tid & 1) << 2;
    // B tile load: 8 rows x 128 cols; each thread: one float4
    const int brow = tid >> 5;
    const int bcol = (tid & 31) << 2;

    const float* Aptr = A + (size_t)(m0 + arow) * K + acol;
    const float* Bptr = B + (size_t)brow * N + n0 + bcol;

    float acc[8][8];
#pragma unroll
    for (int i = 0; i < 8; i++)
#pragma unroll
        for (int j = 0; j < 8; j++) acc[i][j] = 0.0f;

    for (int k0 = 0; k0 < K; k0 += 8) {
        float4 av = *(const float4*)(Aptr + k0);
        As[acol + 0][arow] = av.x;
        As[acol + 1][arow] = av.y;
        As[acol + 2][arow] = av.z;
        As[acol + 3][arow] = av.w;
        *(float4*)&Bs[brow][bcol] = *(const float4*)(Bptr + (size_t)k0 * N);
        __syncthreads();

#pragma unroll
        for (int kk = 0; kk < 8; kk++) {
            float a[8], b[8];
            *(float4*)(a + 0) = *(const float4*)&As[kk][ty * 8 + 0];
            *(float4*)(a + 4) = *(const float4*)&As[kk][ty * 8 + 4];
            *(float4*)(b + 0) = *(const float4*)&Bs[kk][tx * 8 + 0];
            *(float4*)(b + 4) = *(const float4*)&Bs[kk][tx * 8 + 4];
#pragma unroll
            for (int i = 0; i < 8; i++)
#pragma unroll
                for (int j = 0; j < 8; j++)
                    acc[i][j] = fmaf(a[i], b[j], acc[i][j]);
        }
        __syncthreads();
    }

    float* Cptr = C + (size_t)(m0 + ty * 8) * N + n0 + tx * 8;
#pragma unroll
    for (int i = 0; i < 8; i++) {
        *(float4*)(Cptr + (size_t)i * N + 0) =
            make_float4(acc[i][0], acc[i][1], acc[i][2], acc[i][3]);
        *(float4*)(Cptr + (size_t)i * N + 4) =
            make_float4(acc[i][4], acc[i][5], acc[i][6], acc[i][7]);
    }
}

// ---------------- RoPE (in-place), optional fold of 1/sqrt(HD) ----------------
// x layout: [MROWS][heads*128]. Pair (d, d+64), angle = s * 10000^(-d/64).
__global__ void rope_kernel(float* __restrict__ x, int heads, float scale)
{
    const int total = MROWS * heads * 64;
    int idx = blockIdx.x * blockDim.x + threadIdx.x;
    if (idx >= total) return;
    int d = idx & 63;
    int t = idx >> 6;
    int h = t % heads;
    int m = t / heads;
    int s = m & (SEQ - 1);  // position within sequence

    // inv_freq = 10000^(-2d/128) = 2^(-d * log2(10000)/64)
    float e = -(float)d * (13.287712379549449f / 64.0f);
    float inv = exp2f(e);
    float ang = (float)s * inv;
    float sn, cs;
    sincosf(ang, &sn, &cs);

    size_t base = (size_t)m * (heads * 128) + h * 128 + d;
    float lo = x[base];
    float hi = x[base + 64];
    x[base]      = (lo * cs - hi * sn) * scale;
    x[base + 64] = (hi * cs + lo * sn) * scale;
}

// ---------------- Flash attention (causal, GQA) ----------------
// Block: 256 threads (16x16). Tile: 64 q-rows x 64 k-cols, head_dim 128.
// qT/kT staged transposed [128][68] for conflict-free float4 LDS.
#define FPITCH 68
#define FL_SMEM_FLOATS (128 * FPITCH * 2 + 64 * 128 + 64 * FPITCH)
#define FL_SMEM_BYTES (FL_SMEM_FLOATS * 4)

__global__ __launch_bounds__(256, 1)
void flash_kernel(const float* __restrict__ Q, const float* __restrict__ Kg,
                  const float* __restrict__ Vg, float* __restrict__ O)
{
    extern __shared__ float sm[];
    float* qT = sm;                      // [128][68]  qT[c][r]
    float* kT = qT + 128 * FPITCH;       // [128][68]  kT[c][r]
    float* vs = kT + 128 * FPITCH;       // [64][128]  vs[r][c]
    float* ps = vs + 64 * 128;           // [64][68]   ps[r][kj]

    const int qt = (int)gridDim.x - 1 - (int)blockIdx.x;  // heavy tiles first
    const int h = blockIdx.y;
    const int b = blockIdx.z;
    const int g = h >> 2;  // kv head (N_GROUPS = 4)
    const int tid = threadIdx.x;
    const int tx = tid & 15;
    const int ty = tid >> 4;

    const int q0 = qt * 64;
    const float* qbase = Q + (size_t)(b * SEQ) * HIDDEN + h * HD;
    const float* kbase = Kg + (size_t)(b * SEQ) * KVW + g * HD;
    const float* vbase = Vg + (size_t)(b * SEQ) * KVW + g * HD;

    // Load Q tile (transposed into smem). Coalesced global reads.
    for (int i = tid; i < 64 * 128; i += 256) {
        int r = i >> 7;
        int c = i & 127;
        qT[c * FPITCH + r] = qbase[(size_t)(q0 + r) * HIDDEN + c];
    }

    float m_i[4], l_i[4], acc[4][8];
#pragma unroll
    for (int i = 0; i < 4; i++) {
        m_i[i] = -INFINITY;
        l_i[i] = 0.0f;
#pragma unroll
        for (int j = 0; j < 8; j++) acc[i][j] = 0.0f;
    }

    for (int kt = 0; kt <= qt; kt++) {
        __syncthreads();  // previous iteration's reads of kT/vs/ps complete
        const int k0 = kt * 64;
        for (int i = tid; i < 64 * 128; i += 256) {
            int r = i >> 7;
            int c = i & 127;
            size_t gaddr = (size_t)(k0 + r) * KVW + c;
            kT[c * FPITCH + r] = kbase[gaddr];
            vs[r * 128 + c] = vbase[gaddr];
        }
        __syncthreads();

        // ---- scores: S[4][4] = q(rows ty*4+i) . k(cols tx*4+j) ----
        float s_acc[4][4];
#pragma unroll
        for (int i = 0; i < 4; i++)
#pragma unroll
            for (int j = 0; j < 4; j++) s_acc[i][j] = 0.0f;

#pragma unroll 8
        for (int kk = 0; kk < 128; kk++) {
            float4 qa = *(const float4*)(qT + kk * FPITCH + ty * 4);
            float4 ka = *(const float4*)(kT + kk * FPITCH + tx * 4);
            float qv[4] = {qa.x, qa.y, qa.z, qa.w};
            float kv[4] = {ka.x, ka.y, ka.z, ka.w};
#pragma unroll
            for (int i = 0; i < 4; i++)
#pragma unroll
                for (int j = 0; j < 4; j++)
                    s_acc[i][j] = fmaf(qv[i], kv[j], s_acc[i][j]);
        }

        // ---- causal mask (only on diagonal tile) ----
        if (kt == qt) {
#pragma unroll
            for (int i = 0; i < 4; i++) {
                int qi = q0 + ty * 4 + i;
#pragma unroll
                for (int j = 0; j < 4; j++) {
                    int kj = k0 + tx * 4 + j;
                    if (kj > qi) s_acc[i][j] = -INFINITY;
                }
            }
        }

        // ---- online softmax (rows owned by fixed (ty,i); reduce over 16 tx lanes) ----
        float alpha[4];
#pragma unroll
        for (int i = 0; i < 4; i++) {
            float mx = fmaxf(fmaxf(s_acc[i][0], s_acc[i][1]),
                             fmaxf(s_acc[i][2], s_acc[i][3]));
#pragma unroll
            for (int off = 8; off > 0; off >>= 1)
                mx = fmaxf(mx, __shfl_xor_sync(0xffffffffu, mx, off, 16));
            float newm = fmaxf(m_i[i], mx);

            float p[4], rs = 0.0f;
#pragma unroll
            for (int j = 0; j < 4; j++) {
                p[j] = __expf(s_acc[i][j] - newm);
                rs += p[j];
            }
#pragma unroll
            for (int off = 8; off > 0; off >>= 1)
                rs += __shfl_xor_sync(0xffffffffu, rs, off, 16);

            float al = __expf(m_i[i] - newm);
            l_i[i] = l_i[i] * al + rs;
            m_i[i] = newm;
            alpha[i] = al;

            int r = ty * 4 + i;
#pragma unroll
            for (int j = 0; j < 4; j++) ps[r * FPITCH + tx * 4 + j] = p[j];
        }

        // rescale output accumulators
#pragma unroll
        for (int i = 0; i < 4; i++)
#pragma unroll
            for (int j = 0; j < 8; j++) acc[i][j] *= alpha[i];

        __syncthreads();  // ps visible to all

        // ---- PV: O[rows ty*4+i][cols tx*8+j] += P[r][kj] * V[kj][c] ----
#pragma unroll 4
        for (int kj = 0; kj < 64; kj++) {
            float p0 = ps[(ty * 4 + 0) * FPITCH + kj];
            float p1 = ps[(ty * 4 + 1) * FPITCH + kj];
            float p2 = ps[(ty * 4 + 2) * FPITCH + kj];
            float p3 = ps[(ty * 4 + 3) * FPITCH + kj];
            float4 v0 = *(const float4*)(vs + kj * 128 + tx * 8 + 0);
            float4 v1 = *(const float4*)(vs + kj * 128 + tx * 8 + 4);
            acc[0][0] = fmaf(p0, v0.x, acc[0][0]);
            acc[0][1] = fmaf(p0, v0.y, acc[0][1]);
            acc[0][2] = fmaf(p0, v0.z, acc[0][2]);
            acc[0][3] = fmaf(p0, v0.w, acc[0][3]);
            acc[0][4] = fmaf(p0, v1.x, acc[0][4]);
            acc[0][5] = fmaf(p0, v1.y, acc[0][5]);
            acc[0][6] = fmaf(p0, v1.z, acc[0][6]);
            acc[0][7] = fmaf(p0, v1.w, acc[0][7]);
            acc[1][0] = fmaf(p1, v0.x, acc[1][0]);
            acc[1][1] = fmaf(p1, v0.y, acc[1][1]);
            acc[1][2] = fmaf(p1, v0.z, acc[1][2]);
            acc[1][3] = fmaf(p1, v0.w, acc[1][3]);
            acc[1][4] = fmaf(p1, v1.x, acc[1][4]);
            acc[1][5] = fmaf(p1, v1.y, acc[1][5]);
            acc[1][6] = fmaf(p1, v1.z, acc[1][6]);
            acc[1][7] = fmaf(p1, v1.w, acc[1][7]);
            acc[2][0] = fmaf(p2, v0.x, acc[2][0]);
            acc[2][1] = fmaf(p2, v0.y, acc[2][1]);
            acc[2][2] = fmaf(p2, v0.z, acc[2][2]);
            acc[2][3] = fmaf(p2, v0.w, acc[2][3]);
            acc[2][4] = fmaf(p2, v1.x, acc[2][4]);
            acc[2][5] = fmaf(p2, v1.y, acc[2][5]);
            acc[2][6] = fmaf(p2, v1.z, acc[2][6]);
            acc[2][7] = fmaf(p2, v1.w, acc[2][7]);
            acc[3][0] = fmaf(p3, v0.x, acc[3][0]);
            acc[3][1] = fmaf(p3, v0.y, acc[3][1]);
            acc[3][2] = fmaf(p3, v0.z, acc[3][2]);
            acc[3][3] = fmaf(p3, v0.w, acc[3][3]);
            acc[3][4] = fmaf(p3, v1.x, acc[3][4]);
            acc[3][5] = fmaf(p3, v1.y, acc[3][5]);
            acc[3][6] = fmaf(p3, v1.z, acc[3][6]);
            acc[3][7] = fmaf(p3, v1.w, acc[3][7]);
        }
    }

    // ---- epilogue: divide by l, write out ----
    float* obase = O + (size_t)(b * SEQ + q0) * HIDDEN + h * HD;
#pragma unroll
    for (int i = 0; i < 4; i++) {
        float inv_l = 1.0f / l_i[i];
        int r = ty * 4 + i;
        float4 o0 = make_float4(acc[i][0] * inv_l, acc[i][1] * inv_l,
                                acc[i][2] * inv_l, acc[i][3] * inv_l);
        float4 o1 = make_float4(acc[i][4] * inv_l, acc[i][5] * inv_l,
                                acc[i][6] * inv_l, acc[i][7] * inv_l);
        *(float4*)(obase + (size_t)r * HIDDEN + tx * 8 + 0) = o0;
        *(float4*)(obase + (size_t)r * HIDDEN + tx * 8 + 4) = o1;
    }
}

// ---------------- launch ----------------
extern "C" void kernel_launch(void* const* d_in, const int* in_sizes, int n_in,
                              void* d_out, int out_size)
{
    const float* x  = (const float*)d_in[0];  // (2,2048,2048)
    const float* wq = (const float*)d_in[1];  // (2048,2048)
    const float* wk = (const float*)d_in[2];  // (2048,512)
    const float* wv = (const float*)d_in[3];  // (2048,512)
    const float* wo = (const float*)d_in[4];  // (2048,2048)
    float* out = (float*)d_out;

    float *qp, *kp, *vp, *attp;
    cudaGetSymbolAddress((void**)&qp, g_q);
    cudaGetSymbolAddress((void**)&kp, g_k);
    cudaGetSymbolAddress((void**)&vp, g_v);
    cudaGetSymbolAddress((void**)&attp, g_att);

    cudaFuncSetAttribute(flash_kernel,
                         cudaFuncAttributeMaxDynamicSharedMemorySize,
                         FL_SMEM_BYTES);

    // QKV projections
    sgemm128<<<dim3(HIDDEN / 128, MROWS / 128), 256>>>(x, wq, qp, HIDDEN, HIDDEN);
    sgemm128<<<dim3(KVW / 128, MROWS / 128), 256>>>(x, wk, kp, KVW, HIDDEN);
    sgemm128<<<dim3(KVW / 128, MROWS / 128), 256>>>(x, wv, vp, KVW, HIDDEN);

    // RoPE (fold 1/sqrt(HD) into q)
    rope_kernel<<<(MROWS * NHEADS * 64 + 255) / 256, 256>>>(qp, NHEADS, QSCALE);
    rope_kernel<<<(MROWS * NKV * 64 + 255) / 256, 256>>>(kp, NKV, 1.0f);

    // Causal flash attention
    flash_kernel<<<dim3(SEQ / 64, NHEADS, BATCH), 256, FL_SMEM_BYTES>>>(qp, kp, vp, attp);

    // Output projection
    sgemm128<<<dim3(HIDDEN / 128, MROWS / 128), 256>>>(attp, wo, out, HIDDEN, HIDDEN);
}

// round 3
// speedup vs baseline: 1.6325x; 1.6325x over previous
#include <cuda_runtime.h>
#include <cuda_bf16.h>
#include <stdint.h>
#include <math.h>

#define HIDDEN 2048
#define NHEADS 16
#define NKV 4
#define HD 128
#define SEQ 2048
#define BATCH 2
#define MROWS (BATCH * SEQ)   // 4096
#define KVW (NKV * HD)        // 512
#define KDIM 2048
#define QSCALE 0.08838834764831845f  // 1/sqrt(128)

// ---------------- scratch (no allocations allowed) ----------------
__device__ __align__(128) float g_q[MROWS * HIDDEN];
__device__ __align__(128) float g_k[MROWS * KVW];
__device__ __align__(128) float g_v[MROWS * KVW];
__device__ __align__(128) float g_att[MROWS * HIDDEN];
__device__ __align__(128) __nv_bfloat16 g_xhi[MROWS * KDIM];
__device__ __align__(128) __nv_bfloat16 g_xlo[MROWS * KDIM];
__device__ __align__(128) __nv_bfloat16 g_wqhi[HIDDEN * KDIM];  // transposed [N][K]
__device__ __align__(128) __nv_bfloat16 g_wqlo[HIDDEN * KDIM];
__device__ __align__(128) __nv_bfloat16 g_wkhi[KVW * KDIM];
__device__ __align__(128) __nv_bfloat16 g_wklo[KVW * KDIM];
__device__ __align__(128) __nv_bfloat16 g_wvhi[KVW * KDIM];
__device__ __align__(128) __nv_bfloat16 g_wvlo[KVW * KDIM];
__device__ __align__(128) __nv_bfloat16 g_wohi[HIDDEN * KDIM];
__device__ __align__(128) __nv_bfloat16 g_wolo[HIDDEN * KDIM];

// ================= helpers =================
__device__ __forceinline__ uint32_t smem_u32(const void* p) {
    uint32_t a;
    asm("{ .reg .u64 t; cvta.to.shared.u64 t, %1; cvt.u32.u64 %0, t; }"
        : "=r"(a) : "l"(p));
    return a;
}
#define CP_ASYNC16(dst, src) \
    asm volatile("cp.async.cg.shared.global [%0], [%1], 16;" :: "r"(dst), "l"(src) : "memory")
#define CP_COMMIT() asm volatile("cp.async.commit_group;" ::: "memory")
#define CP_WAIT1()  asm volatile("cp.async.wait_group 1;" ::: "memory")

__device__ __forceinline__ void ldsm_x4(uint32_t* r, uint32_t addr) {
    asm volatile("ldmatrix.sync.aligned.m8n8.x4.shared.b16 {%0,%1,%2,%3}, [%4];"
                 : "=r"(r[0]), "=r"(r[1]), "=r"(r[2]), "=r"(r[3]) : "r"(addr));
}
__device__ __forceinline__ void mma16816(float* d, const uint32_t* a, const uint32_t* b) {
    asm volatile("mma.sync.aligned.m16n8k16.row.col.f32.bf16.bf16.f32 "
                 "{%0,%1,%2,%3}, {%4,%5,%6,%7}, {%8,%9}, {%0,%1,%2,%3};"
                 : "+f"(d[0]), "+f"(d[1]), "+f"(d[2]), "+f"(d[3])
                 : "r"(a[0]), "r"(a[1]), "r"(a[2]), "r"(a[3]), "r"(b[0]), "r"(b[1]));
}

// ================= fp32 -> bf16 hi/lo split =================
__global__ void split_f32(const float* __restrict__ x,
                          __nv_bfloat16* __restrict__ hi,
                          __nv_bfloat16* __restrict__ lo, int n4)
{
    int i = blockIdx.x * blockDim.x + threadIdx.x;
    if (i >= n4) return;
    float4 v = ((const float4*)x)[i];
    __nv_bfloat16 h0 = __float2bfloat16(v.x);
    __nv_bfloat16 h1 = __float2bfloat16(v.y);
    __nv_bfloat16 h2 = __float2bfloat16(v.z);
    __nv_bfloat16 h3 = __float2bfloat16(v.w);
    __nv_bfloat16 l0 = __float2bfloat16(v.x - __bfloat162float(h0));
    __nv_bfloat16 l1 = __float2bfloat16(v.y - __bfloat162float(h1));
    __nv_bfloat16 l2 = __float2bfloat16(v.z - __bfloat162float(h2));
    __nv_bfloat16 l3 = __float2bfloat16(v.w - __bfloat162float(h3));
    ((__nv_bfloat162*)hi)[2 * i]     = __nv_bfloat162(h0, h1);
    ((__nv_bfloat162*)hi)[2 * i + 1] = __nv_bfloat162(h2, h3);
    ((__nv_bfloat162*)lo)[2 * i]     = __nv_bfloat162(l0, l1);
    ((__nv_bfloat162*)lo)[2 * i + 1] = __nv_bfloat162(l2, l3);
}

// transpose + split: W [KDIM][Nw] fp32 -> hiT/loT [Nw][KDIM] bf16
__global__ void splitT(const float* __restrict__ W,
                       __nv_bfloat16* __restrict__ hiT,
                       __nv_bfloat16* __restrict__ loT, int Nw)
{
    __shared__ float t[32][33];
    int n0 = blockIdx.x * 32, k0 = blockIdx.y * 32;
    int tx = threadIdx.x, ty = threadIdx.y;
#pragma unroll
    for (int i = 0; i < 32; i += 8)
        t[ty + i][tx] = W[(size_t)(k0 + ty + i) * Nw + n0 + tx];
    __syncthreads();
#pragma unroll
    for (int i = 0; i < 32; i += 8) {
        float v = t[tx][ty + i];
        __nv_bfloat16 h = __float2bfloat16(v);
        size_t o = (size_t)(n0 + ty + i) * KDIM + k0 + tx;
        hiT[o] = h;
        loT[o] = __float2bfloat16(v - __bfloat162float(h));
    }
}

// ================= tensor-core GEMM via mma.sync, bf16x3 split =================
// C[M,N] = A[M,K] @ B[K,N]; A hi/lo [M][K] bf16, B hi/lo transposed [N][K] bf16.
// CTA tile 128x128, BK=32, 256 threads (8 warps, 2x4), warp tile 64x32.
#define BK 32
#define APITCH_B 80                       // bytes per smem row (40 bf16), conflict-free
#define TILE_B (128 * APITCH_B)           // 10240
#define BUF_B (4 * TILE_B)                // Ahi, Alo, Bhi, Blo
#define GSMEM (2 * BUF_B)                 // 81920 double-buffered
#define NCH (KDIM / BK)                   // 64

__global__ __launch_bounds__(256)
void gemm_mma(const __nv_bfloat16* __restrict__ Ahi,
              const __nv_bfloat16* __restrict__ Alo,
              const __nv_bfloat16* __restrict__ Bhi,
              const __nv_bfloat16* __restrict__ Blo,
              float* __restrict__ C, int N)
{
    extern __shared__ char smem[];
    const uint32_t sb = smem_u32(smem);
    const int tid = threadIdx.x;
    const int wid = tid >> 5, lane = tid & 31;
    const int wm = wid >> 2, wn = wid & 3;   // warp grid 2 (m) x 4 (n)
    const int m0 = blockIdx.y << 7;
    const int n0 = blockIdx.x << 7;

    const char* gsrc[4];
    gsrc[0] = (const char*)(Ahi + (size_t)m0 * KDIM);
    gsrc[1] = (const char*)(Alo + (size_t)m0 * KDIM);
    gsrc[2] = (const char*)(Bhi + (size_t)n0 * KDIM);
    gsrc[3] = (const char*)(Blo + (size_t)n0 * KDIM);

    // per-thread load slots: 512 16B-transfers per tile, 2 per thread
    const int r0 = tid >> 2, s0 = tid & 3;          // slot 0: idx = tid
    const int r1 = (tid + 256) >> 2, s1 = tid & 3;  // slot 1: idx = tid+256

    auto load_chunk = [&](int c) {
        const int buf = c & 1;
#pragma unroll
        for (int t = 0; t < 4; t++) {
            const char* gb = gsrc[t] + (size_t)c * (BK * 2);
            uint32_t st = sb + buf * BUF_B + t * TILE_B;
            CP_ASYNC16(st + r0 * APITCH_B + s0 * 16,
                       gb + (size_t)r0 * (KDIM * 2) + s0 * 16);
            CP_ASYNC16(st + r1 * APITCH_B + s1 * 16,
                       gb + (size_t)r1 * (KDIM * 2) + s1 * 16);
        }
    };

    float acc[4][4][4];
#pragma unroll
    for (int i = 0; i < 4; i++)
#pragma unroll
        for (int j = 0; j < 4; j++)
#pragma unroll
            for (int e = 0; e < 4; e++) acc[i][j][e] = 0.0f;

    // fragment smem addresses (offsets within a tile)
    const uint32_t a_off = (uint32_t)((lane & 15) * APITCH_B + (lane >> 4) * 16);
    const int bg = lane >> 3;
    const uint32_t b_off = (uint32_t)(((bg >> 1) * 8 + (lane & 7)) * APITCH_B + (bg & 1) * 16);

    load_chunk(0);
    CP_COMMIT();

    for (int c = 0; c < NCH; ++c) {
        if (c + 1 < NCH) load_chunk(c + 1);
        CP_COMMIT();
        CP_WAIT1();
        __syncthreads();

        const uint32_t base = sb + (c & 1) * BUF_B;
        const int ta[3] = {0, 0, 1}, tb[3] = {2, 3, 2};
#pragma unroll
        for (int p = 0; p < 3; p++) {
            const uint32_t sA = base + ta[p] * TILE_B + (wm * 64) * APITCH_B;
            const uint32_t sB = base + tb[p] * TILE_B + (wn * 32) * APITCH_B;
#pragma unroll
            for (int ks = 0; ks < 2; ks++) {
                const uint32_t koff = ks * 32;
                uint32_t a[4][4], b[4][2];
#pragma unroll
                for (int fm = 0; fm < 4; fm++)
                    ldsm_x4(a[fm], sA + fm * 16 * APITCH_B + koff + a_off);
#pragma unroll
                for (int f2 = 0; f2 < 2; f2++) {
                    uint32_t r[4];
                    ldsm_x4(r, sB + f2 * 16 * APITCH_B + koff + b_off);
                    b[2 * f2][0] = r[0]; b[2 * f2][1] = r[1];
                    b[2 * f2 + 1][0] = r[2]; b[2 * f2 + 1][1] = r[3];
                }
#pragma unroll
                for (int fm = 0; fm < 4; fm++)
#pragma unroll
                    for (int fn = 0; fn < 4; fn++)
                        mma16816(acc[fm][fn], a[fm], b[fn]);
            }
        }
        __syncthreads();
    }

    // epilogue: m16n8 D frag -> thread holds (row, 2c),(row,2c+1),(row+8, 2c),(row+8,2c+1)
    const int erow = lane >> 2;
    const int ecol = (lane & 3) * 2;
#pragma unroll
    for (int fm = 0; fm < 4; fm++) {
#pragma unroll
        for (int fn = 0; fn < 4; fn++) {
            int row = m0 + wm * 64 + fm * 16 + erow;
            int col = n0 + wn * 32 + fn * 8 + ecol;
            *(float2*)(C + (size_t)row * N + col) =
                make_float2(acc[fm][fn][0], acc[fm][fn][1]);
            *(float2*)(C + (size_t)(row + 8) * N + col) =
                make_float2(acc[fm][fn][2], acc[fm][fn][3]);
        }
    }
}

// ---------------- RoPE (in-place), optional fold of 1/sqrt(HD) ----------------
__global__ void rope_kernel(float* __restrict__ x, int heads, float scale)
{
    const int total = MROWS * heads * 64;
    int idx = blockIdx.x * blockDim.x + threadIdx.x;
    if (idx >= total) return;
    int d = idx & 63;
    int t = idx >> 6;
    int h = t % heads;
    int m = t / heads;
    int s = m & (SEQ - 1);

    float e = -(float)d * (13.287712379549449f / 64.0f);
    float inv = exp2f(e);
    float ang = (float)s * inv;
    float sn, cs;
    sincosf(ang, &sn, &cs);

    size_t base = (size_t)m * (heads * 128) + h * 128 + d;
    float lo = x[base];
    float hi = x[base + 64];
    x[base]      = (lo * cs - hi * sn) * scale;
    x[base + 64] = (hi * cs + lo * sn) * scale;
}

// ---------------- Flash attention (causal, GQA), SIMT fp32 ----------------
#define FPITCH 68
#define FL_SMEM_FLOATS (128 * FPITCH * 2 + 64 * 128 + 64 * FPITCH)
#define FL_SMEM_BYTES (FL_SMEM_FLOATS * 4)

__global__ __launch_bounds__(256, 1)
void flash_kernel(const float* __restrict__ Q, const float* __restrict__ Kg,
                  const float* __restrict__ Vg, float* __restrict__ O)
{
    extern __shared__ float sm[];
    float* qT = sm;
    float* kT = qT + 128 * FPITCH;
    float* vs = kT + 128 * FPITCH;
    float* ps = vs + 64 * 128;

    const int qt = (int)gridDim.x - 1 - (int)blockIdx.x;
    const int h = blockIdx.y;
    const int b = blockIdx.z;
    const int g = h >> 2;
    const int tid = threadIdx.x;
    const int tx = tid & 15;
    const int ty = tid >> 4;

    const int q0 = qt * 64;
    const float* qbase = Q + (size_t)(b * SEQ) * HIDDEN + h * HD;
    const float* kbase = Kg + (size_t)(b * SEQ) * KVW + g * HD;
    const float* vbase = Vg + (size_t)(b * SEQ) * KVW + g * HD;

    for (int i = tid; i < 64 * 128; i += 256) {
        int r = i >> 7;
        int c = i & 127;
        qT[c * FPITCH + r] = qbase[(size_t)(q0 + r) * HIDDEN + c];
    }

    float m_i[4], l_i[4], acc[4][8];
#pragma unroll
    for (int i = 0; i < 4; i++) {
        m_i[i] = -INFINITY;
        l_i[i] = 0.0f;
#pragma unroll
        for (int j = 0; j < 8; j++) acc[i][j] = 0.0f;
    }

    for (int kt = 0; kt <= qt; kt++) {
        __syncthreads();
        const int k0 = kt * 64;
        for (int i = tid; i < 64 * 128; i += 256) {
            int r = i >> 7;
            int c = i & 127;
            size_t gaddr = (size_t)(k0 + r) * KVW + c;
            kT[c * FPITCH + r] = kbase[gaddr];
            vs[r * 128 + c] = vbase[gaddr];
        }
        __syncthreads();

        float s_acc[4][4];
#pragma unroll
        for (int i = 0; i < 4; i++)
#pragma unroll
            for (int j = 0; j < 4; j++) s_acc[i][j] = 0.0f;

#pragma unroll 8
        for (int kk = 0; kk < 128; kk++) {
            float4 qa = *(const float4*)(qT + kk * FPITCH + ty * 4);
            float4 ka = *(const float4*)(kT + kk * FPITCH + tx * 4);
            float qv[4] = {qa.x, qa.y, qa.z, qa.w};
            float kv[4] = {ka.x, ka.y, ka.z, ka.w};
#pragma unroll
            for (int i = 0; i < 4; i++)
#pragma unroll
                for (int j = 0; j < 4; j++)
                    s_acc[i][j] = fmaf(qv[i], kv[j], s_acc[i][j]);
        }

        if (kt == qt) {
#pragma unroll
            for (int i = 0; i < 4; i++) {
                int qi = q0 + ty * 4 + i;
#pragma unroll
                for (int j = 0; j < 4; j++) {
                    int kj = k0 + tx * 4 + j;
                    if (kj > qi) s_acc[i][j] = -INFINITY;
                }
            }
        }

        float alpha[4];
#pragma unroll
        for (int i = 0; i < 4; i++) {
            float mx = fmaxf(fmaxf(s_acc[i][0], s_acc[i][1]),
                             fmaxf(s_acc[i][2], s_acc[i][3]));
#pragma unroll
            for (int off = 8; off > 0; off >>= 1)
                mx = fmaxf(mx, __shfl_xor_sync(0xffffffffu, mx, off, 16));
            float newm = fmaxf(m_i[i], mx);

            float p[4], rs = 0.0f;
#pragma unroll
            for (int j = 0; j < 4; j++) {
                p[j] = __expf(s_acc[i][j] - newm);
                rs += p[j];
            }
#pragma unroll
            for (int off = 8; off > 0; off >>= 1)
                rs += __shfl_xor_sync(0xffffffffu, rs, off, 16);

            float al = __expf(m_i[i] - newm);
            l_i[i] = l_i[i] * al + rs;
            m_i[i] = newm;
            alpha[i] = al;

            int r = ty * 4 + i;
#pragma unroll
            for (int j = 0; j < 4; j++) ps[r * FPITCH + tx * 4 + j] = p[j];
        }

#pragma unroll
        for (int i = 0; i < 4; i++)
#pragma unroll
            for (int j = 0; j < 8; j++) acc[i][j] *= alpha[i];

        __syncthreads();

#pragma unroll 4
        for (int kj = 0; kj < 64; kj++) {
            float p0 = ps[(ty * 4 + 0) * FPITCH + kj];
            float p1 = ps[(ty * 4 + 1) * FPITCH + kj];
            float p2 = ps[(ty * 4 + 2) * FPITCH + kj];
            float p3 = ps[(ty * 4 + 3) * FPITCH + kj];
            float4 v0 = *(const float4*)(vs + kj * 128 + tx * 8 + 0);
            float4 v1 = *(const float4*)(vs + kj * 128 + tx * 8 + 4);
            acc[0][0] = fmaf(p0, v0.x, acc[0][0]);
            acc[0][1] = fmaf(p0, v0.y, acc[0][1]);
            acc[0][2] = fmaf(p0, v0.z, acc[0][2]);
            acc[0][3] = fmaf(p0, v0.w, acc[0][3]);
            acc[0][4] = fmaf(p0, v1.x, acc[0][4]);
            acc[0][5] = fmaf(p0, v1.y, acc[0][5]);
            acc[0][6] = fmaf(p0, v1.z, acc[0][6]);
            acc[0][7] = fmaf(p0, v1.w, acc[0][7]);
            acc[1][0] = fmaf(p1, v0.x, acc[1][0]);
            acc[1][1] = fmaf(p1, v0.y, acc[1][1]);
            acc[1][2] = fmaf(p1, v0.z, acc[1][2]);
            acc[1][3] = fmaf(p1, v0.w, acc[1][3]);
            acc[1][4] = fmaf(p1, v1.x, acc[1][4]);
            acc[1][5] = fmaf(p1, v1.y, acc[1][5]);
            acc[1][6] = fmaf(p1, v1.z, acc[1][6]);
            acc[1][7] = fmaf(p1, v1.w, acc[1][7]);
            acc[2][0] = fmaf(p2, v0.x, acc[2][0]);
            acc[2][1] = fmaf(p2, v0.y, acc[2][1]);
            acc[2][2] = fmaf(p2, v0.z, acc[2][2]);
            acc[2][3] = fmaf(p2, v0.w, acc[2][3]);
            acc[2][4] = fmaf(p2, v1.x, acc[2][4]);
            acc[2][5] = fmaf(p2, v1.y, acc[2][5]);
            acc[2][6] = fmaf(p2, v1.z, acc[2][6]);
            acc[2][7] = fmaf(p2, v1.w, acc[2][7]);
            acc[3][0] = fmaf(p3, v0.x, acc[3][0]);
            acc[3][1] = fmaf(p3, v0.y, acc[3][1]);
            acc[3][2] = fmaf(p3, v0.z, acc[3][2]);
            acc[3][3] = fmaf(p3, v0.w, acc[3][3]);
            acc[3][4] = fmaf(p3, v1.x, acc[3][4]);
            acc[3][5] = fmaf(p3, v1.y, acc[3][5]);
            acc[3][6] = fmaf(p3, v1.z, acc[3][6]);
            acc[3][7] = fmaf(p3, v1.w, acc[3][7]);
        }
    }

    float* obase = O + (size_t)(b * SEQ + q0) * HIDDEN + h * HD;
#pragma unroll
    for (int i = 0; i < 4; i++) {
        float inv_l = 1.0f / l_i[i];
        int r = ty * 4 + i;
        float4 o0 = make_float4(acc[i][0] * inv_l, acc[i][1] * inv_l,
                                acc[i][2] * inv_l, acc[i][3] * inv_l);
        float4 o1 = make_float4(acc[i][4] * inv_l, acc[i][5] * inv_l,
                                acc[i][6] * inv_l, acc[i][7] * inv_l);
        *(float4*)(obase + (size_t)r * HIDDEN + tx * 8 + 0) = o0;
        *(float4*)(obase + (size_t)r * HIDDEN + tx * 8 + 4) = o1;
    }
}

// ---------------- launch ----------------
extern "C" void kernel_launch(void* const* d_in, const int* in_sizes, int n_in,
                              void* d_out, int out_size)
{
    const float* x  = (const float*)d_in[0];
    const float* wq = (const float*)d_in[1];
    const float* wk = (const float*)d_in[2];
    const float* wv = (const float*)d_in[3];
    const float* wo = (const float*)d_in[4];
    float* out = (float*)d_out;

    float *qp, *kp, *vp, *attp;
    cudaGetSymbolAddress((void**)&qp, g_q);
    cudaGetSymbolAddress((void**)&kp, g_k);
    cudaGetSymbolAddress((void**)&vp, g_v);
    cudaGetSymbolAddress((void**)&attp, g_att);
    __nv_bfloat16 *xhi, *xlo, *wqhi, *wqlo, *wkhi, *wklo, *wvhi, *wvlo, *wohi, *wolo;
    cudaGetSymbolAddress((void**)&xhi, g_xhi);
    cudaGetSymbolAddress((void**)&xlo, g_xlo);
    cudaGetSymbolAddress((void**)&wqhi, g_wqhi);
    cudaGetSymbolAddress((void**)&wqlo, g_wqlo);
    cudaGetSymbolAddress((void**)&wkhi, g_wkhi);
    cudaGetSymbolAddress((void**)&wklo, g_wklo);
    cudaGetSymbolAddress((void**)&wvhi, g_wvhi);
    cudaGetSymbolAddress((void**)&wvlo, g_wvlo);
    cudaGetSymbolAddress((void**)&wohi, g_wohi);
    cudaGetSymbolAddress((void**)&wolo, g_wolo);

    cudaFuncSetAttribute(flash_kernel,
                         cudaFuncAttributeMaxDynamicSharedMemorySize, FL_SMEM_BYTES);
    cudaFuncSetAttribute(gemm_mma,
                         cudaFuncAttributeMaxDynamicSharedMemorySize, GSMEM);

    // split x and weights into bf16 hi/lo (weights transposed to [N][K])
    const int n4x = MROWS * KDIM / 4;
    split_f32<<<(n4x + 255) / 256, 256>>>(x, xhi, xlo, n4x);
    splitT<<<dim3(HIDDEN / 32, KDIM / 32), dim3(32, 8)>>>(wq, wqhi, wqlo, HIDDEN);
    splitT<<<dim3(KVW / 32, KDIM / 32), dim3(32, 8)>>>(wk, wkhi, wklo, KVW);
    splitT<<<dim3(KVW / 32, KDIM / 32), dim3(32, 8)>>>(wv, wvhi, wvlo, KVW);
    splitT<<<dim3(HIDDEN / 32, KDIM / 32), dim3(32, 8)>>>(wo, wohi, wolo, HIDDEN);

    // QKV projections on tensor cores (mma.sync bf16x3)
    gemm_mma<<<dim3(HIDDEN / 128, MROWS / 128), 256, GSMEM>>>(xhi, xlo, wqhi, wqlo, qp, HIDDEN);
    gemm_mma<<<dim3(KVW / 128, MROWS / 128), 256, GSMEM>>>(xhi, xlo, wkhi, wklo, kp, KVW);
    gemm_mma<<<dim3(KVW / 128, MROWS / 128), 256, GSMEM>>>(xhi, xlo, wvhi, wvlo, vp, KVW);

    // RoPE (fold 1/sqrt(HD) into q)
    rope_kernel<<<(MROWS * NHEADS * 64 + 255) / 256, 256>>>(qp, NHEADS, QSCALE);
    rope_kernel<<<(MROWS * NKV * 64 + 255) / 256, 256>>>(kp, NKV, 1.0f);

    // Causal flash attention (SIMT fp32)
    flash_kernel<<<dim3(SEQ / 64, NHEADS, BATCH), 256, FL_SMEM_BYTES>>>(qp, kp, vp, attp);

    // Output projection on tensor cores
    split_f32<<<(n4x + 255) / 256, 256>>>(attp, xhi, xlo, n4x);
    gemm_mma<<<dim3(HIDDEN / 128, MROWS / 128), 256, GSMEM>>>(xhi, xlo, wohi, wolo, out, HIDDEN);
}

// round 5
// speedup vs baseline: 2.8305x; 1.7339x over previous
#include <cuda_runtime.h>
#include <cuda_bf16.h>
#include <stdint.h>
#include <math.h>

#define HIDDEN 2048
#define NHEADS 16
#define NKV 4
#define HD 128
#define SEQ 2048
#define BATCH 2
#define MROWS (BATCH * SEQ)   // 4096
#define KVW (NKV * HD)        // 512
#define KDIM 2048
#define QSCALE 0.08838834764831845f  // 1/sqrt(128)

// ---------------- scratch (no allocations allowed) ----------------
__device__ __align__(128) float g_q[MROWS * HIDDEN];
__device__ __align__(128) float g_k[MROWS * KVW];
__device__ __align__(128) float g_v[MROWS * KVW];
__device__ __align__(128) float g_att[MROWS * HIDDEN];
__device__ __align__(128) __nv_bfloat16 g_xhi[MROWS * KDIM];
__device__ __align__(128) __nv_bfloat16 g_xlo[MROWS * KDIM];
__device__ __align__(128) __nv_bfloat16 g_khi[MROWS * KVW];
__device__ __align__(128) __nv_bfloat16 g_klo[MROWS * KVW];
__device__ __align__(128) __nv_bfloat16 g_vhi[MROWS * KVW];
__device__ __align__(128) __nv_bfloat16 g_vlo[MROWS * KVW];
__device__ __align__(128) __nv_bfloat16 g_wqhi[HIDDEN * KDIM];  // transposed [N][K]
__device__ __align__(128) __nv_bfloat16 g_wqlo[HIDDEN * KDIM];
__device__ __align__(128) __nv_bfloat16 g_wkhi[KVW * KDIM];
__device__ __align__(128) __nv_bfloat16 g_wklo[KVW * KDIM];
__device__ __align__(128) __nv_bfloat16 g_wvhi[KVW * KDIM];
__device__ __align__(128) __nv_bfloat16 g_wvlo[KVW * KDIM];
__device__ __align__(128) __nv_bfloat16 g_wohi[HIDDEN * KDIM];
__device__ __align__(128) __nv_bfloat16 g_wolo[HIDDEN * KDIM];

// ================= helpers =================
__device__ __forceinline__ uint32_t smem_u32(const void* p) {
    uint32_t a;
    asm("{ .reg .u64 t; cvta.to.shared.u64 t, %1; cvt.u32.u64 %0, t; }"
        : "=r"(a) : "l"(p));
    return a;
}
#define CP_ASYNC16(dst, src) \
    asm volatile("cp.async.cg.shared.global [%0], [%1], 16;" :: "r"(dst), "l"(src) : "memory")
#define CP_COMMIT() asm volatile("cp.async.commit_group;" ::: "memory")
#define CP_WAIT1()  asm volatile("cp.async.wait_group 1;" ::: "memory")
#define CP_WAIT0()  asm volatile("cp.async.wait_group 0;" ::: "memory")

__device__ __forceinline__ void ldsm_x4(uint32_t* r, uint32_t addr) {
    asm volatile("ldmatrix.sync.aligned.m8n8.x4.shared.b16 {%0,%1,%2,%3}, [%4];"
                 : "=r"(r[0]), "=r"(r[1]), "=r"(r[2]), "=r"(r[3]) : "r"(addr));
}
__device__ __forceinline__ void ldsm_x4_t(uint32_t* r, uint32_t addr) {
    asm volatile("ldmatrix.sync.aligned.m8n8.x4.trans.shared.b16 {%0,%1,%2,%3}, [%4];"
                 : "=r"(r[0]), "=r"(r[1]), "=r"(r[2]), "=r"(r[3]) : "r"(addr));
}
__device__ __forceinline__ void mma16816(float* d, const uint32_t* a, const uint32_t* b) {
    asm volatile("mma.sync.aligned.m16n8k16.row.col.f32.bf16.bf16.f32 "
                 "{%0,%1,%2,%3}, {%4,%5,%6,%7}, {%8,%9}, {%0,%1,%2,%3};"
                 : "+f"(d[0]), "+f"(d[1]), "+f"(d[2]), "+f"(d[3])
                 : "r"(a[0]), "r"(a[1]), "r"(a[2]), "r"(a[3]), "r"(b[0]), "r"(b[1]));
}
__device__ __forceinline__ uint32_t packbf(float x, float y) {
    __nv_bfloat162 t;
    t.x = __float2bfloat16_rn(x);
    t.y = __float2bfloat16_rn(y);
    return *(uint32_t*)&t;
}

// ================= fp32 -> bf16 hi/lo split =================
__global__ void split_f32(const float* __restrict__ x,
                          __nv_bfloat16* __restrict__ hi,
                          __nv_bfloat16* __restrict__ lo, int n4)
{
    int i = blockIdx.x * blockDim.x + threadIdx.x;
    if (i >= n4) return;
    float4 v = ((const float4*)x)[i];
    __nv_bfloat16 h0 = __float2bfloat16(v.x);
    __nv_bfloat16 h1 = __float2bfloat16(v.y);
    __nv_bfloat16 h2 = __float2bfloat16(v.z);
    __nv_bfloat16 h3 = __float2bfloat16(v.w);
    __nv_bfloat16 l0 = __float2bfloat16(v.x - __bfloat162float(h0));
    __nv_bfloat16 l1 = __float2bfloat16(v.y - __bfloat162float(h1));
    __nv_bfloat16 l2 = __float2bfloat16(v.z - __bfloat162float(h2));
    __nv_bfloat16 l3 = __float2bfloat16(v.w - __bfloat162float(h3));
    ((__nv_bfloat162*)hi)[2 * i]     = __nv_bfloat162(h0, h1);
    ((__nv_bfloat162*)hi)[2 * i + 1] = __nv_bfloat162(h2, h3);
    ((__nv_bfloat162*)lo)[2 * i]     = __nv_bfloat162(l0, l1);
    ((__nv_bfloat162*)lo)[2 * i + 1] = __nv_bfloat162(l2, l3);
}

// transpose + split: W [KDIM][Nw] fp32 -> hiT/loT [Nw][KDIM] bf16
__global__ void splitT(const float* __restrict__ W,
                       __nv_bfloat16* __restrict__ hiT,
                       __nv_bfloat16* __restrict__ loT, int Nw)
{
    __shared__ float t[32][33];
    int n0 = blockIdx.x * 32, k0 = blockIdx.y * 32;
    int tx = threadIdx.x, ty = threadIdx.y;
#pragma unroll
    for (int i = 0; i < 32; i += 8)
        t[ty + i][tx] = W[(size_t)(k0 + ty + i) * Nw + n0 + tx];
    __syncthreads();
#pragma unroll
    for (int i = 0; i < 32; i += 8) {
        float v = t[tx][ty + i];
        __nv_bfloat16 h = __float2bfloat16(v);
        size_t o = (size_t)(n0 + ty + i) * KDIM + k0 + tx;
        hiT[o] = h;
        loT[o] = __float2bfloat16(v - __bfloat162float(h));
    }
}

// ================= tensor-core GEMM via mma.sync, bf16x3 split =================
#define BK 32
#define APITCH_B 80
#define TILE_B (128 * APITCH_B)
#define BUF_B (4 * TILE_B)
#define GSMEM (2 * BUF_B)
#define NCH (KDIM / BK)

__global__ __launch_bounds__(256)
void gemm_mma(const __nv_bfloat16* __restrict__ Ahi,
              const __nv_bfloat16* __restrict__ Alo,
              const __nv_bfloat16* __restrict__ Bhi,
              const __nv_bfloat16* __restrict__ Blo,
              float* __restrict__ C, int N)
{
    extern __shared__ char smem[];
    const uint32_t sb = smem_u32(smem);
    const int tid = threadIdx.x;
    const int wid = tid >> 5, lane = tid & 31;
    const int wm = wid >> 2, wn = wid & 3;
    const int m0 = blockIdx.y << 7;
    const int n0 = blockIdx.x << 7;

    const char* gsrc[4];
    gsrc[0] = (const char*)(Ahi + (size_t)m0 * KDIM);
    gsrc[1] = (const char*)(Alo + (size_t)m0 * KDIM);
    gsrc[2] = (const char*)(Bhi + (size_t)n0 * KDIM);
    gsrc[3] = (const char*)(Blo + (size_t)n0 * KDIM);

    const int r0 = tid >> 2, s0 = tid & 3;
    const int r1 = (tid + 256) >> 2, s1 = tid & 3;

    auto load_chunk = [&](int c) {
        const int buf = c & 1;
#pragma unroll
        for (int t = 0; t < 4; t++) {
            const char* gb = gsrc[t] + (size_t)c * (BK * 2);
            uint32_t st = sb + buf * BUF_B + t * TILE_B;
            CP_ASYNC16(st + r0 * APITCH_B + s0 * 16,
                       gb + (size_t)r0 * (KDIM * 2) + s0 * 16);
            CP_ASYNC16(st + r1 * APITCH_B + s1 * 16,
                       gb + (size_t)r1 * (KDIM * 2) + s1 * 16);
        }
    };

    float acc[4][4][4];
#pragma unroll
    for (int i = 0; i < 4; i++)
#pragma unroll
        for (int j = 0; j < 4; j++)
#pragma unroll
            for (int e = 0; e < 4; e++) acc[i][j][e] = 0.0f;

    const uint32_t a_off = (uint32_t)((lane & 15) * APITCH_B + (lane >> 4) * 16);
    const int bg = lane >> 3;
    const uint32_t b_off = (uint32_t)(((bg >> 1) * 8 + (lane & 7)) * APITCH_B + (bg & 1) * 16);

    load_chunk(0);
    CP_COMMIT();

    for (int c = 0; c < NCH; ++c) {
        if (c + 1 < NCH) load_chunk(c + 1);
        CP_COMMIT();
        CP_WAIT1();
        __syncthreads();

        const uint32_t base = sb + (c & 1) * BUF_B;
        const int ta[3] = {0, 0, 1}, tb[3] = {2, 3, 2};
#pragma unroll
        for (int p = 0; p < 3; p++) {
            const uint32_t sA = base + ta[p] * TILE_B + (wm * 64) * APITCH_B;
            const uint32_t sB = base + tb[p] * TILE_B + (wn * 32) * APITCH_B;
#pragma unroll
            for (int ks = 0; ks < 2; ks++) {
                const uint32_t koff = ks * 32;
                uint32_t a[4][4], b[4][2];
#pragma unroll
                for (int fm = 0; fm < 4; fm++)
                    ldsm_x4(a[fm], sA + fm * 16 * APITCH_B + koff + a_off);
#pragma unroll
                for (int f2 = 0; f2 < 2; f2++) {
                    uint32_t r[4];
                    ldsm_x4(r, sB + f2 * 16 * APITCH_B + koff + b_off);
                    b[2 * f2][0] = r[0]; b[2 * f2][1] = r[1];
                    b[2 * f2 + 1][0] = r[2]; b[2 * f2 + 1][1] = r[3];
                }
#pragma unroll
                for (int fm = 0; fm < 4; fm++)
#pragma unroll
                    for (int fn = 0; fn < 4; fn++)
                        mma16816(acc[fm][fn], a[fm], b[fn]);
            }
        }
        __syncthreads();
    }

    const int erow = lane >> 2;
    const int ecol = (lane & 3) * 2;
#pragma unroll
    for (int fm = 0; fm < 4; fm++) {
#pragma unroll
        for (int fn = 0; fn < 4; fn++) {
            int row = m0 + wm * 64 + fm * 16 + erow;
            int col = n0 + wn * 32 + fn * 8 + ecol;
            *(float2*)(C + (size_t)row * N + col) =
                make_float2(acc[fm][fn][0], acc[fm][fn][1]);
            *(float2*)(C + (size_t)(row + 8) * N + col) =
                make_float2(acc[fm][fn][2], acc[fm][fn][3]);
        }
    }
}

// ---------------- RoPE (in-place), optional fold of 1/sqrt(HD) ----------------
__global__ void rope_kernel(float* __restrict__ x, int heads, float scale)
{
    const int total = MROWS * heads * 64;
    int idx = blockIdx.x * blockDim.x + threadIdx.x;
    if (idx >= total) return;
    int d = idx & 63;
    int t = idx >> 6;
    int h = t % heads;
    int m = t / heads;
    int s = m & (SEQ - 1);

    float e = -(float)d * (13.287712379549449f / 64.0f);
    float inv = exp2f(e);
    float ang = (float)s * inv;
    float sn, cs;
    sincosf(ang, &sn, &cs);

    size_t base = (size_t)m * (heads * 128) + h * 128 + d;
    float lo = x[base];
    float hi = x[base + 64];
    x[base]      = (lo * cs - hi * sn) * scale;
    x[base + 64] = (hi * cs + lo * sn) * scale;
}

// ================= tensor-core flash attention (causal, GQA) =================
// 256 threads (8 warps); CTA tile: 128 q-rows x 128 k-cols, head_dim 128.
// Warp w owns q-rows [w*16, w*16+16): softmax reductions stay in lane quads.
#define FPB 272                         // smem row pitch bytes (136 bf16)
#define SMB_QHI 0
#define SMB_QLO (128 * FPB)             // 34816
#define SMB_KHI (2 * 128 * FPB)
#define SMB_KLO (3 * 128 * FPB)
#define SMB_VHI (4 * 128 * FPB)
#define SMB_VLO (5 * 128 * FPB)
#define FLASH_SMEM_B (6 * 128 * FPB)    // 208896

__global__ __launch_bounds__(256, 1)
void flash_mma(const __nv_bfloat16* __restrict__ Qhi,
               const __nv_bfloat16* __restrict__ Qlo,
               const __nv_bfloat16* __restrict__ Khi,
               const __nv_bfloat16* __restrict__ Klo,
               const __nv_bfloat16* __restrict__ Vhi,
               const __nv_bfloat16* __restrict__ Vlo,
               float* __restrict__ O)
{
    extern __shared__ char smem[];
    const uint32_t sb = smem_u32(smem);
    const int tid = threadIdx.x;
    const int wid = tid >> 5, lane = tid & 31;
    const int qt = 15 - (int)blockIdx.x;     // heavy tiles first
    const int h = blockIdx.y, b = blockIdx.z;
    const int g = h >> 2;
    const int q0 = qt << 7;

    const uint32_t a_off = (uint32_t)((lane & 15) * FPB + (lane >> 4) * 16);

    // ---- load Q tile (hi/lo) via cp.async ----
    {
        const char* qh = (const char*)(Qhi + (size_t)(b * SEQ + q0) * HIDDEN + h * HD);
        const char* ql = (const char*)(Qlo + (size_t)(b * SEQ + q0) * HIDDEN + h * HD);
#pragma unroll
        for (int i = 0; i < 8; i++) {
            int idx = i * 256 + tid;
            int row = idx >> 4, c = idx & 15;
            CP_ASYNC16(sb + SMB_QHI + row * FPB + c * 16,
                       qh + (size_t)row * (HIDDEN * 2) + c * 16);
            CP_ASYNC16(sb + SMB_QLO + row * FPB + c * 16,
                       ql + (size_t)row * (HIDDEN * 2) + c * 16);
        }
        CP_COMMIT();
    }

    const char* kh_base = (const char*)(Khi + (size_t)(b * SEQ) * KVW + g * HD);
    const char* kl_base = (const char*)(Klo + (size_t)(b * SEQ) * KVW + g * HD);
    const char* vh_base = (const char*)(Vhi + (size_t)(b * SEQ) * KVW + g * HD);
    const char* vl_base = (const char*)(Vlo + (size_t)(b * SEQ) * KVW + g * HD);

    float o[16][4];
#pragma unroll
    for (int nt = 0; nt < 16; nt++)
#pragma unroll
        for (int e = 0; e < 4; e++) o[nt][e] = 0.0f;
    float mrow0 = -INFINITY, mrow1 = -INFINITY, lrow0 = 0.0f, lrow1 = 0.0f;

    for (int kt = 0; kt <= qt; kt++) {
        if (kt > 0) __syncthreads();   // all warps done reading previous K/V
        // ---- load K(hi/lo) + V(hi/lo) tiles ----
        const int k0 = kt << 7;
#pragma unroll
        for (int i = 0; i < 8; i++) {
            int idx = i * 256 + tid;
            int row = idx >> 4, c = idx & 15;
            size_t goff = (size_t)(k0 + row) * (KVW * 2) + c * 16;
            uint32_t soff = row * FPB + c * 16;
            CP_ASYNC16(sb + SMB_KHI + soff, kh_base + goff);
            CP_ASYNC16(sb + SMB_KLO + soff, kl_base + goff);
            CP_ASYNC16(sb + SMB_VHI + soff, vh_base + goff);
            CP_ASYNC16(sb + SMB_VLO + soff, vl_base + goff);
        }
        CP_COMMIT();
        CP_WAIT0();
        __syncthreads();

        // ---- S = Q . K^T  (3 passes hi/lo) ----
        float s[16][4];
#pragma unroll
        for (int nt = 0; nt < 16; nt++)
#pragma unroll
            for (int e = 0; e < 4; e++) s[nt][e] = 0.0f;

#pragma unroll
        for (int ks = 0; ks < 8; ks++) {
            uint32_t ahi[4], alo[4];
            ldsm_x4(ahi, sb + SMB_QHI + (wid * 16) * FPB + ks * 32 + a_off);
            ldsm_x4(alo, sb + SMB_QLO + (wid * 16) * FPB + ks * 32 + a_off);
#pragma unroll
            for (int nt2 = 0; nt2 < 8; nt2++) {
                uint32_t kh[4], kl[4];
                ldsm_x4(kh, sb + SMB_KHI + (nt2 * 16) * FPB + ks * 32 + a_off);
                ldsm_x4(kl, sb + SMB_KLO + (nt2 * 16) * FPB + ks * 32 + a_off);
                uint32_t bh0[2] = {kh[0], kh[2]}, bh1[2] = {kh[1], kh[3]};
                uint32_t bl0[2] = {kl[0], kl[2]}, bl1[2] = {kl[1], kl[3]};
                mma16816(s[2 * nt2],     ahi, bh0);
                mma16816(s[2 * nt2 + 1], ahi, bh1);
                mma16816(s[2 * nt2],     ahi, bl0);
                mma16816(s[2 * nt2 + 1], ahi, bl1);
                mma16816(s[2 * nt2],     alo, bh0);
                mma16816(s[2 * nt2 + 1], alo, bh1);
            }
        }

        // ---- causal mask on diagonal tile ----
        if (kt == qt) {
            const int lr = wid * 16 + (lane >> 2);
            const int lc = 2 * (lane & 3);
#pragma unroll
            for (int nt = 0; nt < 16; nt++) {
                int ln = nt * 8 + lc;
                if (ln > lr)         s[nt][0] = -1e30f;
                if (ln + 1 > lr)     s[nt][1] = -1e30f;
                if (ln > lr + 8)     s[nt][2] = -1e30f;
                if (ln + 1 > lr + 8) s[nt][3] = -1e30f;
            }
        }

        // ---- online softmax (rows gr, gr+8; reduce across lane quad) ----
        float mx0 = -1e30f, mx1 = -1e30f;
#pragma unroll
        for (int nt = 0; nt < 16; nt++) {
            mx0 = fmaxf(mx0, fmaxf(s[nt][0], s[nt][1]));
            mx1 = fmaxf(mx1, fmaxf(s[nt][2], s[nt][3]));
        }
        mx0 = fmaxf(mx0, __shfl_xor_sync(0xffffffffu, mx0, 1));
        mx0 = fmaxf(mx0, __shfl_xor_sync(0xffffffffu, mx0, 2));
        mx1 = fmaxf(mx1, __shfl_xor_sync(0xffffffffu, mx1, 1));
        mx1 = fmaxf(mx1, __shfl_xor_sync(0xffffffffu, mx1, 2));
        const float newm0 = fmaxf(mrow0, mx0);
        const float newm1 = fmaxf(mrow1, mx1);

        float rs0 = 0.0f, rs1 = 0.0f;
#pragma unroll
        for (int nt = 0; nt < 16; nt++) {
            s[nt][0] = __expf(s[nt][0] - newm0);
            s[nt][1] = __expf(s[nt][1] - newm0);
            s[nt][2] = __expf(s[nt][2] - newm1);
            s[nt][3] = __expf(s[nt][3] - newm1);
            rs0 += s[nt][0] + s[nt][1];
            rs1 += s[nt][2] + s[nt][3];
        }
        rs0 += __shfl_xor_sync(0xffffffffu, rs0, 1);
        rs0 += __shfl_xor_sync(0xffffffffu, rs0, 2);
        rs1 += __shfl_xor_sync(0xffffffffu, rs1, 1);
        rs1 += __shfl_xor_sync(0xffffffffu, rs1, 2);

        const float al0 = __expf(mrow0 - newm0);
        const float al1 = __expf(mrow1 - newm1);
        lrow0 = lrow0 * al0 + rs0;
        lrow1 = lrow1 * al1 + rs1;
        mrow0 = newm0;
        mrow1 = newm1;
#pragma unroll
        for (int nt = 0; nt < 16; nt++) {
            o[nt][0] *= al0; o[nt][1] *= al0;
            o[nt][2] *= al1; o[nt][3] *= al1;
        }

        // ---- O += P . V  (P hi/lo in registers, V hi/lo in smem; 3 passes) ----
#pragma unroll
        for (int t = 0; t < 8; t++) {
            float p00 = s[2 * t][0], p01 = s[2 * t][1];
            float p02 = s[2 * t][2], p03 = s[2 * t][3];
            float p10 = s[2 * t + 1][0], p11 = s[2 * t + 1][1];
            float p12 = s[2 * t + 1][2], p13 = s[2 * t + 1][3];
            uint32_t aph[4], apl[4];
            aph[0] = packbf(p00, p01);
            aph[1] = packbf(p02, p03);
            aph[2] = packbf(p10, p11);
            aph[3] = packbf(p12, p13);
            {
                __nv_bfloat162* hp;
                hp = (__nv_bfloat162*)&aph[0];
                apl[0] = packbf(p00 - __bfloat162float(hp->x), p01 - __bfloat162float(hp->y));
                hp = (__nv_bfloat162*)&aph[1];
                apl[1] = packbf(p02 - __bfloat162float(hp->x), p03 - __bfloat162float(hp->y));
                hp = (__nv_bfloat162*)&aph[2];
                apl[2] = packbf(p10 - __bfloat162float(hp->x), p11 - __bfloat162float(hp->y));
                hp = (__nv_bfloat162*)&aph[3];
                apl[3] = packbf(p12 - __bfloat162float(hp->x), p13 - __bfloat162float(hp->y));
            }
#pragma unroll
            for (int nt2 = 0; nt2 < 8; nt2++) {
                uint32_t vh[4], vl[4];
                ldsm_x4_t(vh, sb + SMB_VHI + (t * 16) * FPB + nt2 * 32 + a_off);
                ldsm_x4_t(vl, sb + SMB_VLO + (t * 16) * FPB + nt2 * 32 + a_off);
                uint32_t bh0[2] = {vh[0], vh[1]}, bh1[2] = {vh[2], vh[3]};
                uint32_t bl0[2] = {vl[0], vl[1]}, bl1[2] = {vl[2], vl[3]};
                mma16816(o[2 * nt2],     aph, bh0);
                mma16816(o[2 * nt2 + 1], aph, bh1);
                mma16816(o[2 * nt2],     aph, bl0);
                mma16816(o[2 * nt2 + 1], aph, bl1);
                mma16816(o[2 * nt2],     apl, bh0);
                mma16816(o[2 * nt2 + 1], apl, bh1);
            }
        }
    }

    // ---- epilogue ----
    const float invl0 = 1.0f / lrow0;
    const float invl1 = 1.0f / lrow1;
    const int grow = b * SEQ + q0 + wid * 16 + (lane >> 2);
    float* obase = O + (size_t)grow * HIDDEN + h * HD + 2 * (lane & 3);
#pragma unroll
    for (int nt = 0; nt < 16; nt++) {
        *(float2*)(obase + nt * 8) =
            make_float2(o[nt][0] * invl0, o[nt][1] * invl0);
        *(float2*)(obase + (size_t)8 * HIDDEN + nt * 8) =
            make_float2(o[nt][2] * invl1, o[nt][3] * invl1);
    }
}

// ---------------- launch ----------------
extern "C" void kernel_launch(void* const* d_in, const int* in_sizes, int n_in,
                              void* d_out, int out_size)
{
    const float* x  = (const float*)d_in[0];
    const float* wq = (const float*)d_in[1];
    const float* wk = (const float*)d_in[2];
    const float* wv = (const float*)d_in[3];
    const float* wo = (const float*)d_in[4];
    float* out = (float*)d_out;

    float *qp, *kp, *vp, *attp;
    cudaGetSymbolAddress((void**)&qp, g_q);
    cudaGetSymbolAddress((void**)&kp, g_k);
    cudaGetSymbolAddress((void**)&vp, g_v);
    cudaGetSymbolAddress((void**)&attp, g_att);
    __nv_bfloat16 *xhi, *xlo, *khi, *klo, *vhi, *vlo;
    __nv_bfloat16 *wqhi, *wqlo, *wkhi, *wklo, *wvhi, *wvlo, *wohi, *wolo;
    cudaGetSymbolAddress((void**)&xhi, g_xhi);
    cudaGetSymbolAddress((void**)&xlo, g_xlo);
    cudaGetSymbolAddress((void**)&khi, g_khi);
    cudaGetSymbolAddress((void**)&klo, g_klo);
    cudaGetSymbolAddress((void**)&vhi, g_vhi);
    cudaGetSymbolAddress((void**)&vlo, g_vlo);
    cudaGetSymbolAddress((void**)&wqhi, g_wqhi);
    cudaGetSymbolAddress((void**)&wqlo, g_wqlo);
    cudaGetSymbolAddress((void**)&wkhi, g_wkhi);
    cudaGetSymbolAddress((void**)&wklo, g_wklo);
    cudaGetSymbolAddress((void**)&wvhi, g_wvhi);
    cudaGetSymbolAddress((void**)&wvlo, g_wvlo);
    cudaGetSymbolAddress((void**)&wohi, g_wohi);
    cudaGetSymbolAddress((void**)&wolo, g_wolo);

    cudaFuncSetAttribute(gemm_mma,
                         cudaFuncAttributeMaxDynamicSharedMemorySize, GSMEM);
    cudaFuncSetAttribute(flash_mma,
                         cudaFuncAttributeMaxDynamicSharedMemorySize, FLASH_SMEM_B);

    // split x and weights into bf16 hi/lo (weights transposed to [N][K])
    const int n4x = MROWS * KDIM / 4;
    const int n4k = MROWS * KVW / 4;
    split_f32<<<(n4x + 255) / 256, 256>>>(x, xhi, xlo, n4x);
    splitT<<<dim3(HIDDEN / 32, KDIM / 32), dim3(32, 8)>>>(wq, wqhi, wqlo, HIDDEN);
    splitT<<<dim3(KVW / 32, KDIM / 32), dim3(32, 8)>>>(wk, wkhi, wklo, KVW);
    splitT<<<dim3(KVW / 32, KDIM / 32), dim3(32, 8)>>>(wv, wvhi, wvlo, KVW);
    splitT<<<dim3(HIDDEN / 32, KDIM / 32), dim3(32, 8)>>>(wo, wohi, wolo, HIDDEN);

    // QKV projections on tensor cores (mma.sync bf16x3)
    gemm_mma<<<dim3(HIDDEN / 128, MROWS / 128), 256, GSMEM>>>(xhi, xlo, wqhi, wqlo, qp, HIDDEN);
    gemm_mma<<<dim3(KVW / 128, MROWS / 128), 256, GSMEM>>>(xhi, xlo, wkhi, wklo, kp, KVW);
    gemm_mma<<<dim3(KVW / 128, MROWS / 128), 256, GSMEM>>>(xhi, xlo, wvhi, wvlo, vp, KVW);

    // RoPE (fold 1/sqrt(HD) into q)
    rope_kernel<<<(MROWS * NHEADS * 64 + 255) / 256, 256>>>(qp, NHEADS, QSCALE);
    rope_kernel<<<(MROWS * NKV * 64 + 255) / 256, 256>>>(kp, NKV, 1.0f);

    // split q/k/v (hi/lo); xhi/xlo reused for q
    split_f32<<<(n4x + 255) / 256, 256>>>(qp, xhi, xlo, n4x);
    split_f32<<<(n4k + 255) / 256, 256>>>(kp, khi, klo, n4k);
    split_f32<<<(n4k + 255) / 256, 256>>>(vp, vhi, vlo, n4k);

    // Causal flash attention on tensor cores
    flash_mma<<<dim3(SEQ / 128, NHEADS, BATCH), 256, FLASH_SMEM_B>>>(
        xhi, xlo, khi, klo, vhi, vlo, attp);

    // Output projection on tensor cores (xhi/xlo reused for attp split)
    split_f32<<<(n4x + 255) / 256, 256>>>(attp, xhi, xlo, n4x);
    gemm_mma<<<dim3(HIDDEN / 128, MROWS / 128), 256, GSMEM>>>(xhi, xlo, wohi, wolo, out, HIDDEN);
}

// round 6
// speedup vs baseline: 3.1757x; 1.1219x over previous
#include <cuda_runtime.h>
#include <cuda_bf16.h>
#include <stdint.h>
#include <math.h>

#define HIDDEN 2048
#define NHEADS 16
#define NKV 4
#define HD 128
#define SEQ 2048
#define BATCH 2
#define MROWS (BATCH * SEQ)   // 4096
#define KVW (NKV * HD)        // 512
#define KDIM 2048
#define QSCALE 0.08838834764831845f  // 1/sqrt(128)

// ---------------- scratch (no allocations allowed) ----------------
__device__ __align__(128) float g_q[MROWS * HIDDEN];
__device__ __align__(128) float g_k[MROWS * KVW];
__device__ __align__(128) float g_v[MROWS * KVW];
__device__ __align__(128) __nv_bfloat16 g_xhi[MROWS * KDIM];
__device__ __align__(128) __nv_bfloat16 g_xlo[MROWS * KDIM];
__device__ __align__(128) __nv_bfloat16 g_ahi[MROWS * KDIM];
__device__ __align__(128) __nv_bfloat16 g_alo[MROWS * KDIM];
__device__ __align__(128) __nv_bfloat16 g_khi[MROWS * KVW];
__device__ __align__(128) __nv_bfloat16 g_klo[MROWS * KVW];
__device__ __align__(128) __nv_bfloat16 g_vhi[MROWS * KVW];
__device__ __align__(128) __nv_bfloat16 g_vlo[MROWS * KVW];
__device__ __align__(128) __nv_bfloat16 g_wqhi[HIDDEN * KDIM];  // transposed [N][K]
__device__ __align__(128) __nv_bfloat16 g_wqlo[HIDDEN * KDIM];
__device__ __align__(128) __nv_bfloat16 g_wkhi[KVW * KDIM];
__device__ __align__(128) __nv_bfloat16 g_wklo[KVW * KDIM];
__device__ __align__(128) __nv_bfloat16 g_wvhi[KVW * KDIM];
__device__ __align__(128) __nv_bfloat16 g_wvlo[KVW * KDIM];
__device__ __align__(128) __nv_bfloat16 g_wohi[HIDDEN * KDIM];
__device__ __align__(128) __nv_bfloat16 g_wolo[HIDDEN * KDIM];

// ================= helpers =================
__device__ __forceinline__ uint32_t smem_u32(const void* p) {
    uint32_t a;
    asm("{ .reg .u64 t; cvta.to.shared.u64 t, %1; cvt.u32.u64 %0, t; }"
        : "=r"(a) : "l"(p));
    return a;
}
#define CP_ASYNC16(dst, src) \
    asm volatile("cp.async.cg.shared.global [%0], [%1], 16;" :: "r"(dst), "l"(src) : "memory")
#define CP_COMMIT() asm volatile("cp.async.commit_group;" ::: "memory")
#define CP_WAIT1()  asm volatile("cp.async.wait_group 1;" ::: "memory")
#define CP_WAIT0()  asm volatile("cp.async.wait_group 0;" ::: "memory")

__device__ __forceinline__ void ldsm_x4(uint32_t* r, uint32_t addr) {
    asm volatile("ldmatrix.sync.aligned.m8n8.x4.shared.b16 {%0,%1,%2,%3}, [%4];"
                 : "=r"(r[0]), "=r"(r[1]), "=r"(r[2]), "=r"(r[3]) : "r"(addr));
}
__device__ __forceinline__ void ldsm_x4_t(uint32_t* r, uint32_t addr) {
    asm volatile("ldmatrix.sync.aligned.m8n8.x4.trans.shared.b16 {%0,%1,%2,%3}, [%4];"
                 : "=r"(r[0]), "=r"(r[1]), "=r"(r[2]), "=r"(r[3]) : "r"(addr));
}
__device__ __forceinline__ void mma16816(float* d, const uint32_t* a, const uint32_t* b) {
    asm volatile("mma.sync.aligned.m16n8k16.row.col.f32.bf16.bf16.f32 "
                 "{%0,%1,%2,%3}, {%4,%5,%6,%7}, {%8,%9}, {%0,%1,%2,%3};"
                 : "+f"(d[0]), "+f"(d[1]), "+f"(d[2]), "+f"(d[3])
                 : "r"(a[0]), "r"(a[1]), "r"(a[2]), "r"(a[3]), "r"(b[0]), "r"(b[1]));
}
__device__ __forceinline__ uint32_t packbf(float x, float y) {
    __nv_bfloat162 t;
    t.x = __float2bfloat16_rn(x);
    t.y = __float2bfloat16_rn(y);
    return *(uint32_t*)&t;
}

// ================= fp32 -> bf16 hi/lo split =================
__global__ void split_f32(const float* __restrict__ x,
                          __nv_bfloat16* __restrict__ hi,
                          __nv_bfloat16* __restrict__ lo, int n4)
{
    int i = blockIdx.x * blockDim.x + threadIdx.x;
    if (i >= n4) return;
    float4 v = ((const float4*)x)[i];
    __nv_bfloat16 h0 = __float2bfloat16(v.x);
    __nv_bfloat16 h1 = __float2bfloat16(v.y);
    __nv_bfloat16 h2 = __float2bfloat16(v.z);
    __nv_bfloat16 h3 = __float2bfloat16(v.w);
    __nv_bfloat16 l0 = __float2bfloat16(v.x - __bfloat162float(h0));
    __nv_bfloat16 l1 = __float2bfloat16(v.y - __bfloat162float(h1));
    __nv_bfloat16 l2 = __float2bfloat16(v.z - __bfloat162float(h2));
    __nv_bfloat16 l3 = __float2bfloat16(v.w - __bfloat162float(h3));
    ((__nv_bfloat162*)hi)[2 * i]     = __nv_bfloat162(h0, h1);
    ((__nv_bfloat162*)hi)[2 * i + 1] = __nv_bfloat162(h2, h3);
    ((__nv_bfloat162*)lo)[2 * i]     = __nv_bfloat162(l0, l1);
    ((__nv_bfloat162*)lo)[2 * i + 1] = __nv_bfloat162(l2, l3);
}

// transpose + split: W [KDIM][Nw] fp32 -> hiT/loT [Nw][KDIM] bf16
__global__ void splitT(const float* __restrict__ W,
                       __nv_bfloat16* __restrict__ hiT,
                       __nv_bfloat16* __restrict__ loT, int Nw)
{
    __shared__ float t[32][33];
    int n0 = blockIdx.x * 32, k0 = blockIdx.y * 32;
    int tx = threadIdx.x, ty = threadIdx.y;
#pragma unroll
    for (int i = 0; i < 32; i += 8)
        t[ty + i][tx] = W[(size_t)(k0 + ty + i) * Nw + n0 + tx];
    __syncthreads();
#pragma unroll
    for (int i = 0; i < 32; i += 8) {
        float v = t[tx][ty + i];
        __nv_bfloat16 h = __float2bfloat16(v);
        size_t o = (size_t)(n0 + ty + i) * KDIM + k0 + tx;
        hiT[o] = h;
        loT[o] = __float2bfloat16(v - __bfloat162float(h));
    }
}

// ---------------- RoPE + split fused: fp32 in -> bf16 hi/lo out ----------------
__global__ void rope_split(const float* __restrict__ x,
                           __nv_bfloat16* __restrict__ hi,
                           __nv_bfloat16* __restrict__ lo,
                           int heads, float scale)
{
    const int total = MROWS * heads * 64;
    int idx = blockIdx.x * blockDim.x + threadIdx.x;
    if (idx >= total) return;
    int d = idx & 63;
    int t = idx >> 6;
    int h = t % heads;
    int m = t / heads;
    int s = m & (SEQ - 1);

    float e = -(float)d * (13.287712379549449f / 64.0f);
    float inv = exp2f(e);
    float ang = (float)s * inv;
    float sn, cs;
    sincosf(ang, &sn, &cs);

    size_t base = (size_t)m * (heads * 128) + h * 128 + d;
    float xlo = x[base];
    float xhi = x[base + 64];
    float y0 = (xlo * cs - xhi * sn) * scale;
    float y1 = (xhi * cs + xlo * sn) * scale;

    __nv_bfloat16 h0 = __float2bfloat16(y0);
    __nv_bfloat16 h1 = __float2bfloat16(y1);
    hi[base]      = h0;
    hi[base + 64] = h1;
    lo[base]      = __float2bfloat16(y0 - __bfloat162float(h0));
    lo[base + 64] = __float2bfloat16(y1 - __bfloat162float(h1));
}

// ================= tensor-core GEMM via mma.sync, bf16x3 split =================
#define BK 32
#define APITCH_B 80
#define TILE_B (128 * APITCH_B)
#define BUF_B (4 * TILE_B)
#define GSMEM (2 * BUF_B)
#define NCHG (KDIM / BK)

__global__ __launch_bounds__(256)
void gemm_mma(const __nv_bfloat16* __restrict__ Ahi,
              const __nv_bfloat16* __restrict__ Alo,
              const __nv_bfloat16* __restrict__ Bhi,
              const __nv_bfloat16* __restrict__ Blo,
              float* __restrict__ C, int N)
{
    extern __shared__ char smem[];
    const uint32_t sb = smem_u32(smem);
    const int tid = threadIdx.x;
    const int wid = tid >> 5, lane = tid & 31;
    const int wm = wid >> 2, wn = wid & 3;
    const int m0 = blockIdx.y << 7;
    const int n0 = blockIdx.x << 7;

    const char* gsrc[4];
    gsrc[0] = (const char*)(Ahi + (size_t)m0 * KDIM);
    gsrc[1] = (const char*)(Alo + (size_t)m0 * KDIM);
    gsrc[2] = (const char*)(Bhi + (size_t)n0 * KDIM);
    gsrc[3] = (const char*)(Blo + (size_t)n0 * KDIM);

    const int r0 = tid >> 2, s0 = tid & 3;
    const int r1 = (tid + 256) >> 2, s1 = tid & 3;

    auto load_chunk = [&](int c) {
        const int buf = c & 1;
#pragma unroll
        for (int t = 0; t < 4; t++) {
            const char* gb = gsrc[t] + (size_t)c * (BK * 2);
            uint32_t st = sb + buf * BUF_B + t * TILE_B;
            CP_ASYNC16(st + r0 * APITCH_B + s0 * 16,
                       gb + (size_t)r0 * (KDIM * 2) + s0 * 16);
            CP_ASYNC16(st + r1 * APITCH_B + s1 * 16,
                       gb + (size_t)r1 * (KDIM * 2) + s1 * 16);
        }
    };

    float acc[4][4][4];
#pragma unroll
    for (int i = 0; i < 4; i++)
#pragma unroll
        for (int j = 0; j < 4; j++)
#pragma unroll
            for (int e = 0; e < 4; e++) acc[i][j][e] = 0.0f;

    const uint32_t a_off = (uint32_t)((lane & 15) * APITCH_B + (lane >> 4) * 16);
    const int bg = lane >> 3;
    const uint32_t b_off = (uint32_t)(((bg >> 1) * 8 + (lane & 7)) * APITCH_B + (bg & 1) * 16);

    load_chunk(0);
    CP_COMMIT();

    for (int c = 0; c < NCHG; ++c) {
        if (c + 1 < NCHG) load_chunk(c + 1);
        CP_COMMIT();
        CP_WAIT1();
        __syncthreads();

        const uint32_t base = sb + (c & 1) * BUF_B;
        const uint32_t sAhi = base + 0 * TILE_B + (wm * 64) * APITCH_B;
        const uint32_t sAlo = base + 1 * TILE_B + (wm * 64) * APITCH_B;
        const uint32_t sBhi = base + 2 * TILE_B + (wn * 32) * APITCH_B;
        const uint32_t sBlo = base + 3 * TILE_B + (wn * 32) * APITCH_B;
#pragma unroll
        for (int ks = 0; ks < 2; ks++) {
            const uint32_t koff = ks * 32;
            uint32_t ahi[4][4], alo[4][4], bh[4][2], bl[4][2];
#pragma unroll
            for (int fm = 0; fm < 4; fm++)
                ldsm_x4(ahi[fm], sAhi + fm * 16 * APITCH_B + koff + a_off);
#pragma unroll
            for (int f2 = 0; f2 < 2; f2++) {
                uint32_t r[4];
                ldsm_x4(r, sBhi + f2 * 16 * APITCH_B + koff + b_off);
                bh[2 * f2][0] = r[0]; bh[2 * f2][1] = r[1];
                bh[2 * f2 + 1][0] = r[2]; bh[2 * f2 + 1][1] = r[3];
            }
            // ahi x bhi
#pragma unroll
            for (int fm = 0; fm < 4; fm++)
#pragma unroll
                for (int fn = 0; fn < 4; fn++)
                    mma16816(acc[fm][fn], ahi[fm], bh[fn]);
#pragma unroll
            for (int f2 = 0; f2 < 2; f2++) {
                uint32_t r[4];
                ldsm_x4(r, sBlo + f2 * 16 * APITCH_B + koff + b_off);
                bl[2 * f2][0] = r[0]; bl[2 * f2][1] = r[1];
                bl[2 * f2 + 1][0] = r[2]; bl[2 * f2 + 1][1] = r[3];
            }
            // ahi x blo
#pragma unroll
            for (int fm = 0; fm < 4; fm++)
#pragma unroll
                for (int fn = 0; fn < 4; fn++)
                    mma16816(acc[fm][fn], ahi[fm], bl[fn]);
#pragma unroll
            for (int fm = 0; fm < 4; fm++)
                ldsm_x4(alo[fm], sAlo + fm * 16 * APITCH_B + koff + a_off);
            // alo x bhi
#pragma unroll
            for (int fm = 0; fm < 4; fm++)
#pragma unroll
                for (int fn = 0; fn < 4; fn++)
                    mma16816(acc[fm][fn], alo[fm], bh[fn]);
        }
        __syncthreads();
    }

    const int erow = lane >> 2;
    const int ecol = (lane & 3) * 2;
#pragma unroll
    for (int fm = 0; fm < 4; fm++) {
#pragma unroll
        for (int fn = 0; fn < 4; fn++) {
            int row = m0 + wm * 64 + fm * 16 + erow;
            int col = n0 + wn * 32 + fn * 8 + ecol;
            *(float2*)(C + (size_t)row * N + col) =
                make_float2(acc[fm][fn][0], acc[fm][fn][1]);
            *(float2*)(C + (size_t)(row + 8) * N + col) =
                make_float2(acc[fm][fn][2], acc[fm][fn][3]);
        }
    }
}

// ================= tensor-core flash attention (causal, GQA) =================
// 256 threads (8 warps); q-tile 128 rows, kv-step 64 cols, head_dim 128.
// K/V hi/lo double-buffered (cp.async pipeline); outputs att hi/lo bf16.
#define FPB 272                         // smem row pitch bytes (136 bf16)
#define QTILE_B (128 * FPB)             // 34816
#define KVTILE_B (64 * FPB)             // 17408
#define SMB_QHI 0
#define SMB_QLO QTILE_B
#define SMB_KV  (2 * QTILE_B)           // 8 kv tiles follow (2 bufs x 4)
#define FLASH_SMEM_B (2 * QTILE_B + 8 * KVTILE_B)  // 208896

__global__ __launch_bounds__(256, 1)
void flash_mma(const __nv_bfloat16* __restrict__ Qhi,
               const __nv_bfloat16* __restrict__ Qlo,
               const __nv_bfloat16* __restrict__ Khi,
               const __nv_bfloat16* __restrict__ Klo,
               const __nv_bfloat16* __restrict__ Vhi,
               const __nv_bfloat16* __restrict__ Vlo,
               __nv_bfloat16* __restrict__ Ohi,
               __nv_bfloat16* __restrict__ Olo)
{
    extern __shared__ char smem[];
    const uint32_t sb = smem_u32(smem);
    const int tid = threadIdx.x;
    const int wid = tid >> 5, lane = tid & 31;
    const int qt = 15 - (int)blockIdx.x;     // heavy tiles first
    const int h = blockIdx.y, b = blockIdx.z;
    const int g = h >> 2;
    const int q0 = qt << 7;
    const int ntiles = 2 * qt + 2;           // 64-col kv tiles

    const uint32_t a_off = (uint32_t)((lane & 15) * FPB + (lane >> 4) * 16);

    const char* kh_base = (const char*)(Khi + (size_t)(b * SEQ) * KVW + g * HD);
    const char* kl_base = (const char*)(Klo + (size_t)(b * SEQ) * KVW + g * HD);
    const char* vh_base = (const char*)(Vhi + (size_t)(b * SEQ) * KVW + g * HD);
    const char* vl_base = (const char*)(Vlo + (size_t)(b * SEQ) * KVW + g * HD);

    auto issue_kv = [&](int j) {
        const uint32_t dst = sb + SMB_KV + (j & 1) * (4 * KVTILE_B);
        const int k0 = j << 6;
        const char* srcs[4] = {kh_base, kl_base, vh_base, vl_base};
#pragma unroll
        for (int t = 0; t < 4; t++) {
#pragma unroll
            for (int i = 0; i < 4; i++) {
                int idx = i * 256 + tid;         // 0..1023
                int row = idx >> 4, c = idx & 15;
                CP_ASYNC16(dst + t * KVTILE_B + row * FPB + c * 16,
                           srcs[t] + (size_t)(k0 + row) * (KVW * 2) + c * 16);
            }
        }
    };

    // ---- prologue: Q tiles + first two KV tiles ----
    {
        const char* qh = (const char*)(Qhi + (size_t)(b * SEQ + q0) * HIDDEN + h * HD);
        const char* ql = (const char*)(Qlo + (size_t)(b * SEQ + q0) * HIDDEN + h * HD);
#pragma unroll
        for (int i = 0; i < 8; i++) {
            int idx = i * 256 + tid;
            int row = idx >> 4, c = idx & 15;
            CP_ASYNC16(sb + SMB_QHI + row * FPB + c * 16,
                       qh + (size_t)row * (HIDDEN * 2) + c * 16);
            CP_ASYNC16(sb + SMB_QLO + row * FPB + c * 16,
                       ql + (size_t)row * (HIDDEN * 2) + c * 16);
        }
        CP_COMMIT();
    }
    issue_kv(0);
    CP_COMMIT();
    issue_kv(1);   // ntiles >= 2 always
    CP_COMMIT();

    float o[16][4];
#pragma unroll
    for (int nt = 0; nt < 16; nt++)
#pragma unroll
        for (int e = 0; e < 4; e++) o[nt][e] = 0.0f;
    float mrow0 = -INFINITY, mrow1 = -INFINITY, lrow0 = 0.0f, lrow1 = 0.0f;

    for (int j = 0; j < ntiles; j++) {
        if (j + 1 < ntiles) { CP_WAIT1(); } else { CP_WAIT0(); }
        __syncthreads();

        const uint32_t kvb = sb + SMB_KV + (j & 1) * (4 * KVTILE_B);
        const uint32_t skhi = kvb;
        const uint32_t sklo = kvb + KVTILE_B;
        const uint32_t svhi = kvb + 2 * KVTILE_B;
        const uint32_t svlo = kvb + 3 * KVTILE_B;
        const int k0 = j << 6;

        // ---- S = Q . K^T (3 passes hi/lo), 128 q-rows x 64 k-cols ----
        float s[8][4];
#pragma unroll
        for (int nt = 0; nt < 8; nt++)
#pragma unroll
            for (int e = 0; e < 4; e++) s[nt][e] = 0.0f;

#pragma unroll
        for (int ks = 0; ks < 8; ks++) {
            uint32_t ahi[4], alo[4];
            ldsm_x4(ahi, sb + SMB_QHI + (wid * 16) * FPB + ks * 32 + a_off);
            ldsm_x4(alo, sb + SMB_QLO + (wid * 16) * FPB + ks * 32 + a_off);
#pragma unroll
            for (int nt2 = 0; nt2 < 4; nt2++) {
                uint32_t kh[4], kl[4];
                ldsm_x4(kh, skhi + (nt2 * 16) * FPB + ks * 32 + a_off);
                ldsm_x4(kl, sklo + (nt2 * 16) * FPB + ks * 32 + a_off);
                uint32_t bh0[2] = {kh[0], kh[2]}, bh1[2] = {kh[1], kh[3]};
                uint32_t bl0[2] = {kl[0], kl[2]}, bl1[2] = {kl[1], kl[3]};
                mma16816(s[2 * nt2],     ahi, bh0);
                mma16816(s[2 * nt2 + 1], ahi, bh1);
                mma16816(s[2 * nt2],     ahi, bl0);
                mma16816(s[2 * nt2 + 1], ahi, bl1);
                mma16816(s[2 * nt2],     alo, bh0);
                mma16816(s[2 * nt2 + 1], alo, bh1);
            }
        }

        // ---- causal mask (last two kv tiles of the diagonal block) ----
        if (k0 + 64 > q0) {
            const int rq = q0 + wid * 16 + (lane >> 2) - k0;
            const int lc = 2 * (lane & 3);
#pragma unroll
            for (int nt = 0; nt < 8; nt++) {
                int ln = nt * 8 + lc;
                if (ln > rq)         s[nt][0] = -1e30f;
                if (ln + 1 > rq)     s[nt][1] = -1e30f;
                if (ln > rq + 8)     s[nt][2] = -1e30f;
                if (ln + 1 > rq + 8) s[nt][3] = -1e30f;
            }
        }

        // ---- online softmax ----
        float mx0 = -1e30f, mx1 = -1e30f;
#pragma unroll
        for (int nt = 0; nt < 8; nt++) {
            mx0 = fmaxf(mx0, fmaxf(s[nt][0], s[nt][1]));
            mx1 = fmaxf(mx1, fmaxf(s[nt][2], s[nt][3]));
        }
        mx0 = fmaxf(mx0, __shfl_xor_sync(0xffffffffu, mx0, 1));
        mx0 = fmaxf(mx0, __shfl_xor_sync(0xffffffffu, mx0, 2));
        mx1 = fmaxf(mx1, __shfl_xor_sync(0xffffffffu, mx1, 1));
        mx1 = fmaxf(mx1, __shfl_xor_sync(0xffffffffu, mx1, 2));
        const float newm0 = fmaxf(mrow0, mx0);
        const float newm1 = fmaxf(mrow1, mx1);

        float rs0 = 0.0f, rs1 = 0.0f;
#pragma unroll
        for (int nt = 0; nt < 8; nt++) {
            s[nt][0] = __expf(s[nt][0] - newm0);
            s[nt][1] = __expf(s[nt][1] - newm0);
            s[nt][2] = __expf(s[nt][2] - newm1);
            s[nt][3] = __expf(s[nt][3] - newm1);
            rs0 += s[nt][0] + s[nt][1];
            rs1 += s[nt][2] + s[nt][3];
        }
        rs0 += __shfl_xor_sync(0xffffffffu, rs0, 1);
        rs0 += __shfl_xor_sync(0xffffffffu, rs0, 2);
        rs1 += __shfl_xor_sync(0xffffffffu, rs1, 1);
        rs1 += __shfl_xor_sync(0xffffffffu, rs1, 2);

        const float al0 = __expf(mrow0 - newm0);
        const float al1 = __expf(mrow1 - newm1);
        lrow0 = lrow0 * al0 + rs0;
        lrow1 = lrow1 * al1 + rs1;
        mrow0 = newm0;
        mrow1 = newm1;
#pragma unroll
        for (int nt = 0; nt < 16; nt++) {
            o[nt][0] *= al0; o[nt][1] *= al0;
            o[nt][2] *= al1; o[nt][3] *= al1;
        }

        // ---- O += P . V  (P hi/lo in registers, V hi/lo in smem; 3 passes) ----
#pragma unroll
        for (int t = 0; t < 4; t++) {
            float p00 = s[2 * t][0], p01 = s[2 * t][1];
            float p02 = s[2 * t][2], p03 = s[2 * t][3];
            float p10 = s[2 * t + 1][0], p11 = s[2 * t + 1][1];
            float p12 = s[2 * t + 1][2], p13 = s[2 * t + 1][3];
            uint32_t aph[4], apl[4];
            aph[0] = packbf(p00, p01);
            aph[1] = packbf(p02, p03);
            aph[2] = packbf(p10, p11);
            aph[3] = packbf(p12, p13);
            {
                __nv_bfloat162* hp;
                hp = (__nv_bfloat162*)&aph[0];
                apl[0] = packbf(p00 - __bfloat162float(hp->x), p01 - __bfloat162float(hp->y));
                hp = (__nv_bfloat162*)&aph[1];
                apl[1] = packbf(p02 - __bfloat162float(hp->x), p03 - __bfloat162float(hp->y));
                hp = (__nv_bfloat162*)&aph[2];
                apl[2] = packbf(p10 - __bfloat162float(hp->x), p11 - __bfloat162float(hp->y));
                hp = (__nv_bfloat162*)&aph[3];
                apl[3] = packbf(p12 - __bfloat162float(hp->x), p13 - __bfloat162float(hp->y));
            }
#pragma unroll
            for (int nt2 = 0; nt2 < 8; nt2++) {
                uint32_t vh[4], vl[4];
                ldsm_x4_t(vh, svhi + (t * 16) * FPB + nt2 * 32 + a_off);
                ldsm_x4_t(vl, svlo + (t * 16) * FPB + nt2 * 32 + a_off);
                uint32_t bh0[2] = {vh[0], vh[1]}, bh1[2] = {vh[2], vh[3]};
                uint32_t bl0[2] = {vl[0], vl[1]}, bl1[2] = {vl[2], vl[3]};
                mma16816(o[2 * nt2],     aph, bh0);
                mma16816(o[2 * nt2 + 1], aph, bh1);
                mma16816(o[2 * nt2],     aph, bl0);
                mma16816(o[2 * nt2 + 1], aph, bl1);
                mma16816(o[2 * nt2],     apl, bh0);
                mma16816(o[2 * nt2 + 1], apl, bh1);
            }
        }

        __syncthreads();               // done reading buffer (j & 1)
        if (j + 2 < ntiles) {
            issue_kv(j + 2);
            CP_COMMIT();
        }
    }

    // ---- epilogue: normalize, split to hi/lo bf16, write ----
    const float invl0 = 1.0f / lrow0;
    const float invl1 = 1.0f / lrow1;
    const int grow = b * SEQ + q0 + wid * 16 + (lane >> 2);
    const size_t cbase = (size_t)grow * HIDDEN + h * HD + 2 * (lane & 3);
#pragma unroll
    for (int nt = 0; nt < 16; nt++) {
        float v0 = o[nt][0] * invl0, v1 = o[nt][1] * invl0;
        float v2 = o[nt][2] * invl1, v3 = o[nt][3] * invl1;
        uint32_t h01 = packbf(v0, v1);
        uint32_t h23 = packbf(v2, v3);
        __nv_bfloat162* hp01 = (__nv_bfloat162*)&h01;
        __nv_bfloat162* hp23 = (__nv_bfloat162*)&h23;
        uint32_t l01 = packbf(v0 - __bfloat162float(hp01->x),
                              v1 - __bfloat162float(hp01->y));
        uint32_t l23 = packbf(v2 - __bfloat162float(hp23->x),
                              v3 - __bfloat162float(hp23->y));
        *(uint32_t*)(Ohi + cbase + nt * 8) = h01;
        *(uint32_t*)(Olo + cbase + nt * 8) = l01;
        *(uint32_t*)(Ohi + cbase + (size_t)8 * HIDDEN + nt * 8) = h23;
        *(uint32_t*)(Olo + cbase + (size_t)8 * HIDDEN + nt * 8) = l23;
    }
}

// ---------------- launch ----------------
extern "C" void kernel_launch(void* const* d_in, const int* in_sizes, int n_in,
                              void* d_out, int out_size)
{
    const float* x  = (const float*)d_in[0];
    const float* wq = (const float*)d_in[1];
    const float* wk = (const float*)d_in[2];
    const float* wv = (const float*)d_in[3];
    const float* wo = (const float*)d_in[4];
    float* out = (float*)d_out;

    float *qp, *kp, *vp;
    cudaGetSymbolAddress((void**)&qp, g_q);
    cudaGetSymbolAddress((void**)&kp, g_k);
    cudaGetSymbolAddress((void**)&vp, g_v);
    __nv_bfloat16 *xhi, *xlo, *ahi, *alo, *khi, *klo, *vhi, *vlo;
    __nv_bfloat16 *wqhi, *wqlo, *wkhi, *wklo, *wvhi, *wvlo, *wohi, *wolo;
    cudaGetSymbolAddress((void**)&xhi, g_xhi);
    cudaGetSymbolAddress((void**)&xlo, g_xlo);
    cudaGetSymbolAddress((void**)&ahi, g_ahi);
    cudaGetSymbolAddress((void**)&alo, g_alo);
    cudaGetSymbolAddress((void**)&khi, g_khi);
    cudaGetSymbolAddress((void**)&klo, g_klo);
    cudaGetSymbolAddress((void**)&vhi, g_vhi);
    cudaGetSymbolAddress((void**)&vlo, g_vlo);
    cudaGetSymbolAddress((void**)&wqhi, g_wqhi);
    cudaGetSymbolAddress((void**)&wqlo, g_wqlo);
    cudaGetSymbolAddress((void**)&wkhi, g_wkhi);
    cudaGetSymbolAddress((void**)&wklo, g_wklo);
    cudaGetSymbolAddress((void**)&wvhi, g_wvhi);
    cudaGetSymbolAddress((void**)&wvlo, g_wvlo);
    cudaGetSymbolAddress((void**)&wohi, g_wohi);
    cudaGetSymbolAddress((void**)&wolo, g_wolo);

    cudaFuncSetAttribute(gemm_mma,
                         cudaFuncAttributeMaxDynamicSharedMemorySize, GSMEM);
    cudaFuncSetAttribute(flash_mma,
                         cudaFuncAttributeMaxDynamicSharedMemorySize, FLASH_SMEM_B);

    // split x and weights into bf16 hi/lo (weights transposed to [N][K])
    const int n4x = MROWS * KDIM / 4;
    const int n4k = MROWS * KVW / 4;
    split_f32<<<(n4x + 255) / 256, 256>>>(x, xhi, xlo, n4x);
    splitT<<<dim3(HIDDEN / 32, KDIM / 32), dim3(32, 8)>>>(wq, wqhi, wqlo, HIDDEN);
    splitT<<<dim3(KVW / 32, KDIM / 32), dim3(32, 8)>>>(wk, wkhi, wklo, KVW);
    splitT<<<dim3(KVW / 32, KDIM / 32), dim3(32, 8)>>>(wv, wvhi, wvlo, KVW);
    splitT<<<dim3(HIDDEN / 32, KDIM / 32), dim3(32, 8)>>>(wo, wohi, wolo, HIDDEN);

    // QKV projections on tensor cores (mma.sync bf16x3)
    gemm_mma<<<dim3(HIDDEN / 128, MROWS / 128), 256, GSMEM>>>(xhi, xlo, wqhi, wqlo, qp, HIDDEN);
    gemm_mma<<<dim3(KVW / 128, MROWS / 128), 256, GSMEM>>>(xhi, xlo, wkhi, wklo, kp, KVW);
    gemm_mma<<<dim3(KVW / 128, MROWS / 128), 256, GSMEM>>>(xhi, xlo, wvhi, wvlo, vp, KVW);

    // RoPE fused with hi/lo split (q scaled by 1/sqrt(HD)); v split directly
    rope_split<<<(MROWS * NHEADS * 64 + 255) / 256, 256>>>(qp, xhi, xlo, NHEADS, QSCALE);
    rope_split<<<(MROWS * NKV * 64 + 255) / 256, 256>>>(kp, khi, klo, NKV, 1.0f);
    split_f32<<<(n4k + 255) / 256, 256>>>(vp, vhi, vlo, n4k);

    // Causal flash attention on tensor cores (writes att hi/lo directly)
    flash_mma<<<dim3(SEQ / 128, NHEADS, BATCH), 256, FLASH_SMEM_B>>>(
        xhi, xlo, khi, klo, vhi, vlo, ahi, alo);

    // Output projection on tensor cores
    gemm_mma<<<dim3(HIDDEN / 128, MROWS / 128), 256, GSMEM>>>(ahi, alo, wohi, wolo, out, HIDDEN);
}

// round 7
// speedup vs baseline: 3.2376x; 1.0195x over previous
#include <cuda_runtime.h>
#include <cuda_bf16.h>
#include <stdint.h>
#include <math.h>

#define HIDDEN 2048
#define NHEADS 16
#define NKV 4
#define HD 128
#define SEQ 2048
#define BATCH 2
#define MROWS (BATCH * SEQ)   // 4096
#define KVW (NKV * HD)        // 512
#define KDIM 2048
#define QSCALE 0.08838834764831845f  // 1/sqrt(128)

// ---------------- scratch (no allocations allowed) ----------------
__device__ __align__(128) float g_q[MROWS * HIDDEN];
__device__ __align__(128) float g_k[MROWS * KVW];
__device__ __align__(128) float g_v[MROWS * KVW];
__device__ __align__(128) __nv_bfloat16 g_xhi[MROWS * KDIM];
__device__ __align__(128) __nv_bfloat16 g_xlo[MROWS * KDIM];
__device__ __align__(128) __nv_bfloat16 g_ahi[MROWS * KDIM];
__device__ __align__(128) __nv_bfloat16 g_alo[MROWS * KDIM];
__device__ __align__(128) __nv_bfloat16 g_khi[MROWS * KVW];
__device__ __align__(128) __nv_bfloat16 g_klo[MROWS * KVW];
__device__ __align__(128) __nv_bfloat16 g_vhi[MROWS * KVW];
__device__ __align__(128) __nv_bfloat16 g_vlo[MROWS * KVW];
__device__ __align__(128) __nv_bfloat16 g_wqhi[HIDDEN * KDIM];  // transposed [N][K]
__device__ __align__(128) __nv_bfloat16 g_wqlo[HIDDEN * KDIM];
__device__ __align__(128) __nv_bfloat16 g_wkhi[KVW * KDIM];
__device__ __align__(128) __nv_bfloat16 g_wklo[KVW * KDIM];
__device__ __align__(128) __nv_bfloat16 g_wvhi[KVW * KDIM];
__device__ __align__(128) __nv_bfloat16 g_wvlo[KVW * KDIM];
__device__ __align__(128) __nv_bfloat16 g_wohi[HIDDEN * KDIM];
__device__ __align__(128) __nv_bfloat16 g_wolo[HIDDEN * KDIM];

// ================= helpers =================
__device__ __forceinline__ uint32_t smem_u32(const void* p) {
    uint32_t a;
    asm("{ .reg .u64 t; cvta.to.shared.u64 t, %1; cvt.u32.u64 %0, t; }"
        : "=r"(a) : "l"(p));
    return a;
}
#define CP_ASYNC16(dst, src) \
    asm volatile("cp.async.cg.shared.global [%0], [%1], 16;" :: "r"(dst), "l"(src) : "memory")
#define CP_COMMIT() asm volatile("cp.async.commit_group;" ::: "memory")
#define CP_WAIT1()  asm volatile("cp.async.wait_group 1;" ::: "memory")
#define CP_WAIT0()  asm volatile("cp.async.wait_group 0;" ::: "memory")

__device__ __forceinline__ void ldsm_x4(uint32_t* r, uint32_t addr) {
    asm volatile("ldmatrix.sync.aligned.m8n8.x4.shared.b16 {%0,%1,%2,%3}, [%4];"
                 : "=r"(r[0]), "=r"(r[1]), "=r"(r[2]), "=r"(r[3]) : "r"(addr));
}
__device__ __forceinline__ void ldsm_x4_t(uint32_t* r, uint32_t addr) {
    asm volatile("ldmatrix.sync.aligned.m8n8.x4.trans.shared.b16 {%0,%1,%2,%3}, [%4];"
                 : "=r"(r[0]), "=r"(r[1]), "=r"(r[2]), "=r"(r[3]) : "r"(addr));
}
__device__ __forceinline__ void mma16816(float* d, const uint32_t* a, const uint32_t* b) {
    asm volatile("mma.sync.aligned.m16n8k16.row.col.f32.bf16.bf16.f32 "
                 "{%0,%1,%2,%3}, {%4,%5,%6,%7}, {%8,%9}, {%0,%1,%2,%3};"
                 : "+f"(d[0]), "+f"(d[1]), "+f"(d[2]), "+f"(d[3])
                 : "r"(a[0]), "r"(a[1]), "r"(a[2]), "r"(a[3]), "r"(b[0]), "r"(b[1]));
}
__device__ __forceinline__ uint32_t packbf(float x, float y) {
    __nv_bfloat162 t;
    t.x = __float2bfloat16_rn(x);
    t.y = __float2bfloat16_rn(y);
    return *(uint32_t*)&t;
}

// ================= fp32 -> bf16 hi/lo split =================
__global__ void split_f32(const float* __restrict__ x,
                          __nv_bfloat16* __restrict__ hi,
                          __nv_bfloat16* __restrict__ lo, int n4)
{
    int i = blockIdx.x * blockDim.x + threadIdx.x;
    if (i >= n4) return;
    float4 v = ((const float4*)x)[i];
    __nv_bfloat16 h0 = __float2bfloat16(v.x);
    __nv_bfloat16 h1 = __float2bfloat16(v.y);
    __nv_bfloat16 h2 = __float2bfloat16(v.z);
    __nv_bfloat16 h3 = __float2bfloat16(v.w);
    __nv_bfloat16 l0 = __float2bfloat16(v.x - __bfloat162float(h0));
    __nv_bfloat16 l1 = __float2bfloat16(v.y - __bfloat162float(h1));
    __nv_bfloat16 l2 = __float2bfloat16(v.z - __bfloat162float(h2));
    __nv_bfloat16 l3 = __float2bfloat16(v.w - __bfloat162float(h3));
    ((__nv_bfloat162*)hi)[2 * i]     = __nv_bfloat162(h0, h1);
    ((__nv_bfloat162*)hi)[2 * i + 1] = __nv_bfloat162(h2, h3);
    ((__nv_bfloat162*)lo)[2 * i]     = __nv_bfloat162(l0, l1);
    ((__nv_bfloat162*)lo)[2 * i + 1] = __nv_bfloat162(l2, l3);
}

// transpose + split: W [KDIM][Nw] fp32 -> hiT/loT [Nw][KDIM] bf16
__global__ void splitT(const float* __restrict__ W,
                       __nv_bfloat16* __restrict__ hiT,
                       __nv_bfloat16* __restrict__ loT, int Nw)
{
    __shared__ float t[32][33];
    int n0 = blockIdx.x * 32, k0 = blockIdx.y * 32;
    int tx = threadIdx.x, ty = threadIdx.y;
#pragma unroll
    for (int i = 0; i < 32; i += 8)
        t[ty + i][tx] = W[(size_t)(k0 + ty + i) * Nw + n0 + tx];
    __syncthreads();
#pragma unroll
    for (int i = 0; i < 32; i += 8) {
        float v = t[tx][ty + i];
        __nv_bfloat16 h = __float2bfloat16(v);
        size_t o = (size_t)(n0 + ty + i) * KDIM + k0 + tx;
        hiT[o] = h;
        loT[o] = __float2bfloat16(v - __bfloat162float(h));
    }
}

// ---------------- RoPE + split fused: fp32 in -> bf16 hi/lo out ----------------
__global__ void rope_split(const float* __restrict__ x,
                           __nv_bfloat16* __restrict__ hi,
                           __nv_bfloat16* __restrict__ lo,
                           int heads, float scale)
{
    const int total = MROWS * heads * 64;
    int idx = blockIdx.x * blockDim.x + threadIdx.x;
    if (idx >= total) return;
    int d = idx & 63;
    int t = idx >> 6;
    int h = t % heads;
    int m = t / heads;
    int s = m & (SEQ - 1);

    float e = -(float)d * (13.287712379549449f / 64.0f);
    float inv = exp2f(e);
    float ang = (float)s * inv;
    float sn, cs;
    sincosf(ang, &sn, &cs);

    size_t base = (size_t)m * (heads * 128) + h * 128 + d;
    float xlo = x[base];
    float xhi = x[base + 64];
    float y0 = (xlo * cs - xhi * sn) * scale;
    float y1 = (xhi * cs + xlo * sn) * scale;

    __nv_bfloat16 h0 = __float2bfloat16(y0);
    __nv_bfloat16 h1 = __float2bfloat16(y1);
    hi[base]      = h0;
    hi[base + 64] = h1;
    lo[base]      = __float2bfloat16(y0 - __bfloat162float(h0));
    lo[base + 64] = __float2bfloat16(y1 - __bfloat162float(h1));
}

// ================= tensor-core GEMM via mma.sync, bf16x3 split =================
// blockIdx.z selects among up to 2 (B, C) problem sets (for fused K/V proj).
#define BK 32
#define APITCH_B 80
#define TILE_B (128 * APITCH_B)
#define BUF_B (4 * TILE_B)
#define GSMEM (2 * BUF_B)
#define NCHG (KDIM / BK)

struct GemmProb {
    const __nv_bfloat16* Bhi;
    const __nv_bfloat16* Blo;
    float* C;
    int N;
};

__global__ __launch_bounds__(256, 2)
void gemm_mma(const __nv_bfloat16* __restrict__ Ahi,
              const __nv_bfloat16* __restrict__ Alo,
              GemmProb p0, GemmProb p1)
{
    extern __shared__ char smem[];
    const uint32_t sb = smem_u32(smem);
    const int tid = threadIdx.x;
    const int wid = tid >> 5, lane = tid & 31;
    const int wm = wid >> 2, wn = wid & 3;
    const int m0 = blockIdx.y << 7;
    const int n0 = blockIdx.x << 7;

    const GemmProb* p = blockIdx.z ? &p1 : &p0;
    const __nv_bfloat16* Bhi = p->Bhi;
    const __nv_bfloat16* Blo = p->Blo;
    float* C = p->C;
    const int N = p->N;

    const char* gsrc[4];
    gsrc[0] = (const char*)(Ahi + (size_t)m0 * KDIM);
    gsrc[1] = (const char*)(Alo + (size_t)m0 * KDIM);
    gsrc[2] = (const char*)(Bhi + (size_t)n0 * KDIM);
    gsrc[3] = (const char*)(Blo + (size_t)n0 * KDIM);

    const int r0 = tid >> 2, s0 = tid & 3;
    const int r1 = (tid + 256) >> 2, s1 = tid & 3;

    auto load_chunk = [&](int c) {
        const int buf = c & 1;
#pragma unroll
        for (int t = 0; t < 4; t++) {
            const char* gb = gsrc[t] + (size_t)c * (BK * 2);
            uint32_t st = sb + buf * BUF_B + t * TILE_B;
            CP_ASYNC16(st + r0 * APITCH_B + s0 * 16,
                       gb + (size_t)r0 * (KDIM * 2) + s0 * 16);
            CP_ASYNC16(st + r1 * APITCH_B + s1 * 16,
                       gb + (size_t)r1 * (KDIM * 2) + s1 * 16);
        }
    };

    float acc[4][4][4];
#pragma unroll
    for (int i = 0; i < 4; i++)
#pragma unroll
        for (int j = 0; j < 4; j++)
#pragma unroll
            for (int e = 0; e < 4; e++) acc[i][j][e] = 0.0f;

    const uint32_t a_off = (uint32_t)((lane & 15) * APITCH_B + (lane >> 4) * 16);
    const int bg = lane >> 3;
    const uint32_t b_off = (uint32_t)(((bg >> 1) * 8 + (lane & 7)) * APITCH_B + (bg & 1) * 16);

    load_chunk(0);
    CP_COMMIT();

    for (int c = 0; c < NCHG; ++c) {
        if (c + 1 < NCHG) load_chunk(c + 1);
        CP_COMMIT();
        CP_WAIT1();
        __syncthreads();

        const uint32_t base = sb + (c & 1) * BUF_B;
        const uint32_t sAhi = base + 0 * TILE_B + (wm * 64) * APITCH_B;
        const uint32_t sAlo = base + 1 * TILE_B + (wm * 64) * APITCH_B;
        const uint32_t sBhi = base + 2 * TILE_B + (wn * 32) * APITCH_B;
        const uint32_t sBlo = base + 3 * TILE_B + (wn * 32) * APITCH_B;
#pragma unroll
        for (int ks = 0; ks < 2; ks++) {
            const uint32_t koff = ks * 32;
            uint32_t ahi[4][4], bh[4][2];
#pragma unroll
            for (int fm = 0; fm < 4; fm++)
                ldsm_x4(ahi[fm], sAhi + fm * 16 * APITCH_B + koff + a_off);
#pragma unroll
            for (int f2 = 0; f2 < 2; f2++) {
                uint32_t r[4];
                ldsm_x4(r, sBhi + f2 * 16 * APITCH_B + koff + b_off);
                bh[2 * f2][0] = r[0]; bh[2 * f2][1] = r[1];
                bh[2 * f2 + 1][0] = r[2]; bh[2 * f2 + 1][1] = r[3];
            }
            // ahi x bhi
#pragma unroll
            for (int fm = 0; fm < 4; fm++)
#pragma unroll
                for (int fn = 0; fn < 4; fn++)
                    mma16816(acc[fm][fn], ahi[fm], bh[fn]);
            {
                uint32_t bl[4][2];
#pragma unroll
                for (int f2 = 0; f2 < 2; f2++) {
                    uint32_t r[4];
                    ldsm_x4(r, sBlo + f2 * 16 * APITCH_B + koff + b_off);
                    bl[2 * f2][0] = r[0]; bl[2 * f2][1] = r[1];
                    bl[2 * f2 + 1][0] = r[2]; bl[2 * f2 + 1][1] = r[3];
                }
                // ahi x blo
#pragma unroll
                for (int fm = 0; fm < 4; fm++)
#pragma unroll
                    for (int fn = 0; fn < 4; fn++)
                        mma16816(acc[fm][fn], ahi[fm], bl[fn]);
            }
            // alo x bhi (ahi registers dead; reuse)
            uint32_t alo[4][4];
#pragma unroll
            for (int fm = 0; fm < 4; fm++)
                ldsm_x4(alo[fm], sAlo + fm * 16 * APITCH_B + koff + a_off);
#pragma unroll
            for (int fm = 0; fm < 4; fm++)
#pragma unroll
                for (int fn = 0; fn < 4; fn++)
                    mma16816(acc[fm][fn], alo[fm], bh[fn]);
        }
        __syncthreads();
    }

    const int erow = lane >> 2;
    const int ecol = (lane & 3) * 2;
#pragma unroll
    for (int fm = 0; fm < 4; fm++) {
#pragma unroll
        for (int fn = 0; fn < 4; fn++) {
            int row = m0 + wm * 64 + fm * 16 + erow;
            int col = n0 + wn * 32 + fn * 8 + ecol;
            *(float2*)(C + (size_t)row * N + col) =
                make_float2(acc[fm][fn][0], acc[fm][fn][1]);
            *(float2*)(C + (size_t)(row + 8) * N + col) =
                make_float2(acc[fm][fn][2], acc[fm][fn][3]);
        }
    }
}

// ================= tensor-core flash attention (causal, GQA) =================
#define FPB 272                         // smem row pitch bytes (136 bf16)
#define QTILE_B (128 * FPB)             // 34816
#define KVTILE_B (64 * FPB)             // 17408
#define SMB_QHI 0
#define SMB_QLO QTILE_B
#define SMB_KV  (2 * QTILE_B)           // 8 kv tiles follow (2 bufs x 4)
#define FLASH_SMEM_B (2 * QTILE_B + 8 * KVTILE_B)  // 208896

__global__ __launch_bounds__(256, 1)
void flash_mma(const __nv_bfloat16* __restrict__ Qhi,
               const __nv_bfloat16* __restrict__ Qlo,
               const __nv_bfloat16* __restrict__ Khi,
               const __nv_bfloat16* __restrict__ Klo,
               const __nv_bfloat16* __restrict__ Vhi,
               const __nv_bfloat16* __restrict__ Vlo,
               __nv_bfloat16* __restrict__ Ohi,
               __nv_bfloat16* __restrict__ Olo)
{
    extern __shared__ char smem[];
    const uint32_t sb = smem_u32(smem);
    const int tid = threadIdx.x;
    const int wid = tid >> 5, lane = tid & 31;
    const int qt = 15 - (int)blockIdx.x;     // heavy tiles first
    const int h = blockIdx.y, b = blockIdx.z;
    const int g = h >> 2;
    const int q0 = qt << 7;
    const int ntiles = 2 * qt + 2;           // 64-col kv tiles

    const uint32_t a_off = (uint32_t)((lane & 15) * FPB + (lane >> 4) * 16);

    const char* kh_base = (const char*)(Khi + (size_t)(b * SEQ) * KVW + g * HD);
    const char* kl_base = (const char*)(Klo + (size_t)(b * SEQ) * KVW + g * HD);
    const char* vh_base = (const char*)(Vhi + (size_t)(b * SEQ) * KVW + g * HD);
    const char* vl_base = (const char*)(Vlo + (size_t)(b * SEQ) * KVW + g * HD);

    auto issue_kv = [&](int j) {
        const uint32_t dst = sb + SMB_KV + (j & 1) * (4 * KVTILE_B);
        const int k0 = j << 6;
        const char* srcs[4] = {kh_base, kl_base, vh_base, vl_base};
#pragma unroll
        for (int t = 0; t < 4; t++) {
#pragma unroll
            for (int i = 0; i < 4; i++) {
                int idx = i * 256 + tid;         // 0..1023
                int row = idx >> 4, c = idx & 15;
                CP_ASYNC16(dst + t * KVTILE_B + row * FPB + c * 16,
                           srcs[t] + (size_t)(k0 + row) * (KVW * 2) + c * 16);
            }
        }
    };

    // ---- prologue: Q tiles + first two KV tiles ----
    {
        const char* qh = (const char*)(Qhi + (size_t)(b * SEQ + q0) * HIDDEN + h * HD);
        const char* ql = (const char*)(Qlo + (size_t)(b * SEQ + q0) * HIDDEN + h * HD);
#pragma unroll
        for (int i = 0; i < 8; i++) {
            int idx = i * 256 + tid;
            int row = idx >> 4, c = idx & 15;
            CP_ASYNC16(sb + SMB_QHI + row * FPB + c * 16,
                       qh + (size_t)row * (HIDDEN * 2) + c * 16);
            CP_ASYNC16(sb + SMB_QLO + row * FPB + c * 16,
                       ql + (size_t)row * (HIDDEN * 2) + c * 16);
        }
        CP_COMMIT();
    }
    issue_kv(0);
    CP_COMMIT();
    issue_kv(1);   // ntiles >= 2 always
    CP_COMMIT();

    float o[16][4];
#pragma unroll
    for (int nt = 0; nt < 16; nt++)
#pragma unroll
        for (int e = 0; e < 4; e++) o[nt][e] = 0.0f;
    float mrow0 = -INFINITY, mrow1 = -INFINITY, lrow0 = 0.0f, lrow1 = 0.0f;

    for (int j = 0; j < ntiles; j++) {
        if (j + 1 < ntiles) { CP_WAIT1(); } else { CP_WAIT0(); }
        __syncthreads();

        const uint32_t kvb = sb + SMB_KV + (j & 1) * (4 * KVTILE_B);
        const uint32_t skhi = kvb;
        const uint32_t sklo = kvb + KVTILE_B;
        const uint32_t svhi = kvb + 2 * KVTILE_B;
        const uint32_t svlo = kvb + 3 * KVTILE_B;
        const int k0 = j << 6;

        // ---- S = Q . K^T (3 passes hi/lo), 128 q-rows x 64 k-cols ----
        float s[8][4];
#pragma unroll
        for (int nt = 0; nt < 8; nt++)
#pragma unroll
            for (int e = 0; e < 4; e++) s[nt][e] = 0.0f;

#pragma unroll
        for (int ks = 0; ks < 8; ks++) {
            uint32_t ahi[4], alo[4];
            ldsm_x4(ahi, sb + SMB_QHI + (wid * 16) * FPB + ks * 32 + a_off);
            ldsm_x4(alo, sb + SMB_QLO + (wid * 16) * FPB + ks * 32 + a_off);
#pragma unroll
            for (int nt2 = 0; nt2 < 4; nt2++) {
                uint32_t kh[4], kl[4];
                ldsm_x4(kh, skhi + (nt2 * 16) * FPB + ks * 32 + a_off);
                ldsm_x4(kl, sklo + (nt2 * 16) * FPB + ks * 32 + a_off);
                uint32_t bh0[2] = {kh[0], kh[2]}, bh1[2] = {kh[1], kh[3]};
                uint32_t bl0[2] = {kl[0], kl[2]}, bl1[2] = {kl[1], kl[3]};
                mma16816(s[2 * nt2],     ahi, bh0);
                mma16816(s[2 * nt2 + 1], ahi, bh1);
                mma16816(s[2 * nt2],     ahi, bl0);
                mma16816(s[2 * nt2 + 1], ahi, bl1);
                mma16816(s[2 * nt2],     alo, bh0);
                mma16816(s[2 * nt2 + 1], alo, bh1);
            }
        }

        // ---- causal mask (diagonal block tiles) ----
        if (k0 + 64 > q0) {
            const int rq = q0 + wid * 16 + (lane >> 2) - k0;
            const int lc = 2 * (lane & 3);
#pragma unroll
            for (int nt = 0; nt < 8; nt++) {
                int ln = nt * 8 + lc;
                if (ln > rq)         s[nt][0] = -1e30f;
                if (ln + 1 > rq)     s[nt][1] = -1e30f;
                if (ln > rq + 8)     s[nt][2] = -1e30f;
                if (ln + 1 > rq + 8) s[nt][3] = -1e30f;
            }
        }

        // ---- online softmax ----
        float mx0 = -1e30f, mx1 = -1e30f;
#pragma unroll
        for (int nt = 0; nt < 8; nt++) {
            mx0 = fmaxf(mx0, fmaxf(s[nt][0], s[nt][1]));
            mx1 = fmaxf(mx1, fmaxf(s[nt][2], s[nt][3]));
        }
        mx0 = fmaxf(mx0, __shfl_xor_sync(0xffffffffu, mx0, 1));
        mx0 = fmaxf(mx0, __shfl_xor_sync(0xffffffffu, mx0, 2));
        mx1 = fmaxf(mx1, __shfl_xor_sync(0xffffffffu, mx1, 1));
        mx1 = fmaxf(mx1, __shfl_xor_sync(0xffffffffu, mx1, 2));
        const float newm0 = fmaxf(mrow0, mx0);
        const float newm1 = fmaxf(mrow1, mx1);

        float rs0 = 0.0f, rs1 = 0.0f;
#pragma unroll
        for (int nt = 0; nt < 8; nt++) {
            s[nt][0] = __expf(s[nt][0] - newm0);
            s[nt][1] = __expf(s[nt][1] - newm0);
            s[nt][2] = __expf(s[nt][2] - newm1);
            s[nt][3] = __expf(s[nt][3] - newm1);
            rs0 += s[nt][0] + s[nt][1];
            rs1 += s[nt][2] + s[nt][3];
        }
        rs0 += __shfl_xor_sync(0xffffffffu, rs0, 1);
        rs0 += __shfl_xor_sync(0xffffffffu, rs0, 2);
        rs1 += __shfl_xor_sync(0xffffffffu, rs1, 1);
        rs1 += __shfl_xor_sync(0xffffffffu, rs1, 2);

        const float al0 = __expf(mrow0 - newm0);
        const float al1 = __expf(mrow1 - newm1);
        lrow0 = lrow0 * al0 + rs0;
        lrow1 = lrow1 * al1 + rs1;
        mrow0 = newm0;
        mrow1 = newm1;
#pragma unroll
        for (int nt = 0; nt < 16; nt++) {
            o[nt][0] *= al0; o[nt][1] *= al0;
            o[nt][2] *= al1; o[nt][3] *= al1;
        }

        // ---- O += P . V  (P hi/lo in registers, V hi/lo in smem; 3 passes) ----
#pragma unroll
        for (int t = 0; t < 4; t++) {
            float p00 = s[2 * t][0], p01 = s[2 * t][1];
            float p02 = s[2 * t][2], p03 = s[2 * t][3];
            float p10 = s[2 * t + 1][0], p11 = s[2 * t + 1][1];
            float p12 = s[2 * t + 1][2], p13 = s[2 * t + 1][3];
            uint32_t aph[4], apl[4];
            aph[0] = packbf(p00, p01);
            aph[1] = packbf(p02, p03);
            aph[2] = packbf(p10, p11);
            aph[3] = packbf(p12, p13);
            {
                __nv_bfloat162* hp;
                hp = (__nv_bfloat162*)&aph[0];
                apl[0] = packbf(p00 - __bfloat162float(hp->x), p01 - __bfloat162float(hp->y));
                hp = (__nv_bfloat162*)&aph[1];
                apl[1] = packbf(p02 - __bfloat162float(hp->x), p03 - __bfloat162float(hp->y));
                hp = (__nv_bfloat162*)&aph[2];
                apl[2] = packbf(p10 - __bfloat162float(hp->x), p11 - __bfloat162float(hp->y));
                hp = (__nv_bfloat162*)&aph[3];
                apl[3] = packbf(p12 - __bfloat162float(hp->x), p13 - __bfloat162float(hp->y));
            }
#pragma unroll
            for (int nt2 = 0; nt2 < 8; nt2++) {
                uint32_t vh[4], vl[4];
                ldsm_x4_t(vh, svhi + (t * 16) * FPB + nt2 * 32 + a_off);
                ldsm_x4_t(vl, svlo + (t * 16) * FPB + nt2 * 32 + a_off);
                uint32_t bh0[2] = {vh[0], vh[1]}, bh1[2] = {vh[2], vh[3]};
                uint32_t bl0[2] = {vl[0], vl[1]}, bl1[2] = {vl[2], vl[3]};
                mma16816(o[2 * nt2],     aph, bh0);
                mma16816(o[2 * nt2 + 1], aph, bh1);
                mma16816(o[2 * nt2],     aph, bl0);
                mma16816(o[2 * nt2 + 1], aph, bl1);
                mma16816(o[2 * nt2],     apl, bh0);
                mma16816(o[2 * nt2 + 1], apl, bh1);
            }
        }

        __syncthreads();               // done reading buffer (j & 1)
        if (j + 2 < ntiles) {
            issue_kv(j + 2);
            CP_COMMIT();
        }
    }

    // ---- epilogue: normalize, split to hi/lo bf16, write ----
    const float invl0 = 1.0f / lrow0;
    const float invl1 = 1.0f / lrow1;
    const int grow = b * SEQ + q0 + wid * 16 + (lane >> 2);
    const size_t cbase = (size_t)grow * HIDDEN + h * HD + 2 * (lane & 3);
#pragma unroll
    for (int nt = 0; nt < 16; nt++) {
        float v0 = o[nt][0] * invl0, v1 = o[nt][1] * invl0;
        float v2 = o[nt][2] * invl1, v3 = o[nt][3] * invl1;
        uint32_t h01 = packbf(v0, v1);
        uint32_t h23 = packbf(v2, v3);
        __nv_bfloat162* hp01 = (__nv_bfloat162*)&h01;
        __nv_bfloat162* hp23 = (__nv_bfloat162*)&h23;
        uint32_t l01 = packbf(v0 - __bfloat162float(hp01->x),
                              v1 - __bfloat162float(hp01->y));
        uint32_t l23 = packbf(v2 - __bfloat162float(hp23->x),
                              v3 - __bfloat162float(hp23->y));
        *(uint32_t*)(Ohi + cbase + nt * 8) = h01;
        *(uint32_t*)(Olo + cbase + nt * 8) = l01;
        *(uint32_t*)(Ohi + cbase + (size_t)8 * HIDDEN + nt * 8) = h23;
        *(uint32_t*)(Olo + cbase + (size_t)8 * HIDDEN + nt * 8) = l23;
    }
}

// ---------------- launch ----------------
extern "C" void kernel_launch(void* const* d_in, const int* in_sizes, int n_in,
                              void* d_out, int out_size)
{
    const float* x  = (const float*)d_in[0];
    const float* wq = (const float*)d_in[1];
    const float* wk = (const float*)d_in[2];
    const float* wv = (const float*)d_in[3];
    const float* wo = (const float*)d_in[4];
    float* out = (float*)d_out;

    float *qp, *kp, *vp;
    cudaGetSymbolAddress((void**)&qp, g_q);
    cudaGetSymbolAddress((void**)&kp, g_k);
    cudaGetSymbolAddress((void**)&vp, g_v);
    __nv_bfloat16 *xhi, *xlo, *ahi, *alo, *khi, *klo, *vhi, *vlo;
    __nv_bfloat16 *wqhi, *wqlo, *wkhi, *wklo, *wvhi, *wvlo, *wohi, *wolo;
    cudaGetSymbolAddress((void**)&xhi, g_xhi);
    cudaGetSymbolAddress((void**)&xlo, g_xlo);
    cudaGetSymbolAddress((void**)&ahi, g_ahi);
    cudaGetSymbolAddress((void**)&alo, g_alo);
    cudaGetSymbolAddress((void**)&khi, g_khi);
    cudaGetSymbolAddress((void**)&klo, g_klo);
    cudaGetSymbolAddress((void**)&vhi, g_vhi);
    cudaGetSymbolAddress((void**)&vlo, g_vlo);
    cudaGetSymbolAddress((void**)&wqhi, g_wqhi);
    cudaGetSymbolAddress((void**)&wqlo, g_wqlo);
    cudaGetSymbolAddress((void**)&wkhi, g_wkhi);
    cudaGetSymbolAddress((void**)&wklo, g_wklo);
    cudaGetSymbolAddress((void**)&wvhi, g_wvhi);
    cudaGetSymbolAddress((void**)&wvlo, g_wvlo);
    cudaGetSymbolAddress((void**)&wohi, g_wohi);
    cudaGetSymbolAddress((void**)&wolo, g_wolo);

    cudaFuncSetAttribute(gemm_mma,
                         cudaFuncAttributeMaxDynamicSharedMemorySize, GSMEM);
    cudaFuncSetAttribute(flash_mma,
                         cudaFuncAttributeMaxDynamicSharedMemorySize, FLASH_SMEM_B);

    // split x and weights into bf16 hi/lo (weights transposed to [N][K])
    const int n4x = MROWS * KDIM / 4;
    const int n4k = MROWS * KVW / 4;
    split_f32<<<(n4x + 255) / 256, 256>>>(x, xhi, xlo, n4x);
    splitT<<<dim3(HIDDEN / 32, KDIM / 32), dim3(32, 8)>>>(wq, wqhi, wqlo, HIDDEN);
    splitT<<<dim3(KVW / 32, KDIM / 32), dim3(32, 8)>>>(wk, wkhi, wklo, KVW);
    splitT<<<dim3(KVW / 32, KDIM / 32), dim3(32, 8)>>>(wv, wvhi, wvlo, KVW);
    splitT<<<dim3(HIDDEN / 32, KDIM / 32), dim3(32, 8)>>>(wo, wohi, wolo, HIDDEN);

    GemmProb pq  = {wqhi, wqlo, qp, HIDDEN};
    GemmProb pk  = {wkhi, wklo, kp, KVW};
    GemmProb pv  = {wvhi, wvlo, vp, KVW};
    GemmProb po  = {wohi, wolo, out, HIDDEN};

    // Q projection (z=1 unused -> pass pq twice)
    gemm_mma<<<dim3(HIDDEN / 128, MROWS / 128, 1), 256, GSMEM>>>(xhi, xlo, pq, pq);
    // K and V projections fused into one launch (z selects)
    gemm_mma<<<dim3(KVW / 128, MROWS / 128, 2), 256, GSMEM>>>(xhi, xlo, pk, pv);

    // RoPE fused with hi/lo split (q scaled by 1/sqrt(HD)); v split directly
    rope_split<<<(MROWS * NHEADS * 64 + 255) / 256, 256>>>(qp, xhi, xlo, NHEADS, QSCALE);
    rope_split<<<(MROWS * NKV * 64 + 255) / 256, 256>>>(kp, khi, klo, NKV, 1.0f);
    split_f32<<<(n4k + 255) / 256, 256>>>(vp, vhi, vlo, n4k);

    // Causal flash attention on tensor cores (writes att hi/lo directly)
    flash_mma<<<dim3(SEQ / 128, NHEADS, BATCH), 256, FLASH_SMEM_B>>>(
        xhi, xlo, khi, klo, vhi, vlo, ahi, alo);

    // Output projection on tensor cores
    gemm_mma<<<dim3(HIDDEN / 128, MROWS / 128, 1), 256, GSMEM>>>(ahi, alo, po, po);
}

// round 8
// speedup vs baseline: 3.3396x; 1.0315x over previous
#include <cuda_runtime.h>
#include <cuda_bf16.h>
#include <stdint.h>
#include <math.h>

#define HIDDEN 2048
#define NHEADS 16
#define NKV 4
#define HD 128
#define SEQ 2048
#define BATCH 2
#define MROWS (BATCH * SEQ)   // 4096
#define KVW (NKV * HD)        // 512
#define KDIM 2048
// 1/sqrt(128) * log2(e)  (exp2-based softmax)
#define QSCALE_L2E 0.1275174500772518f

// ---------------- scratch (no allocations allowed) ----------------
__device__ __align__(128) float g_q[MROWS * HIDDEN];
__device__ __align__(128) float g_k[MROWS * KVW];
__device__ __align__(128) float g_v[MROWS * KVW];
__device__ __align__(128) __nv_bfloat16 g_xhi[MROWS * KDIM];
__device__ __align__(128) __nv_bfloat16 g_xlo[MROWS * KDIM];
__device__ __align__(128) __nv_bfloat16 g_ahi[MROWS * KDIM];
__device__ __align__(128) __nv_bfloat16 g_alo[MROWS * KDIM];
__device__ __align__(128) __nv_bfloat16 g_khi[MROWS * KVW];
__device__ __align__(128) __nv_bfloat16 g_klo[MROWS * KVW];
__device__ __align__(128) __nv_bfloat16 g_vhi[MROWS * KVW];
__device__ __align__(128) __nv_bfloat16 g_vlo[MROWS * KVW];
__device__ __align__(128) __nv_bfloat16 g_wqhi[HIDDEN * KDIM];  // transposed [N][K]
__device__ __align__(128) __nv_bfloat16 g_wqlo[HIDDEN * KDIM];
__device__ __align__(128) __nv_bfloat16 g_wkhi[KVW * KDIM];
__device__ __align__(128) __nv_bfloat16 g_wklo[KVW * KDIM];
__device__ __align__(128) __nv_bfloat16 g_wvhi[KVW * KDIM];
__device__ __align__(128) __nv_bfloat16 g_wvlo[KVW * KDIM];
__device__ __align__(128) __nv_bfloat16 g_wohi[HIDDEN * KDIM];
__device__ __align__(128) __nv_bfloat16 g_wolo[HIDDEN * KDIM];

// ================= helpers =================
__device__ __forceinline__ uint32_t smem_u32(const void* p) {
    uint32_t a;
    asm("{ .reg .u64 t; cvta.to.shared.u64 t, %1; cvt.u32.u64 %0, t; }"
        : "=r"(a) : "l"(p));
    return a;
}
#define CP_ASYNC16(dst, src) \
    asm volatile("cp.async.cg.shared.global [%0], [%1], 16;" :: "r"(dst), "l"(src) : "memory")
#define CP_COMMIT() asm volatile("cp.async.commit_group;" ::: "memory")
#define CP_WAIT1()  asm volatile("cp.async.wait_group 1;" ::: "memory")
#define CP_WAIT0()  asm volatile("cp.async.wait_group 0;" ::: "memory")

__device__ __forceinline__ void ldsm_x4(uint32_t* r, uint32_t addr) {
    asm volatile("ldmatrix.sync.aligned.m8n8.x4.shared.b16 {%0,%1,%2,%3}, [%4];"
                 : "=r"(r[0]), "=r"(r[1]), "=r"(r[2]), "=r"(r[3]) : "r"(addr));
}
__device__ __forceinline__ void ldsm_x4_t(uint32_t* r, uint32_t addr) {
    asm volatile("ldmatrix.sync.aligned.m8n8.x4.trans.shared.b16 {%0,%1,%2,%3}, [%4];"
                 : "=r"(r[0]), "=r"(r[1]), "=r"(r[2]), "=r"(r[3]) : "r"(addr));
}
__device__ __forceinline__ void mma16816(float* d, const uint32_t* a, const uint32_t* b) {
    asm volatile("mma.sync.aligned.m16n8k16.row.col.f32.bf16.bf16.f32 "
                 "{%0,%1,%2,%3}, {%4,%5,%6,%7}, {%8,%9}, {%0,%1,%2,%3};"
                 : "+f"(d[0]), "+f"(d[1]), "+f"(d[2]), "+f"(d[3])
                 : "r"(a[0]), "r"(a[1]), "r"(a[2]), "r"(a[3]), "r"(b[0]), "r"(b[1]));
}
__device__ __forceinline__ uint32_t packbf(float x, float y) {
    __nv_bfloat162 t;
    t.x = __float2bfloat16_rn(x);
    t.y = __float2bfloat16_rn(y);
    return *(uint32_t*)&t;
}
__device__ __forceinline__ float fexp2(float x) {
    float y;
    asm("ex2.approx.f32 %0, %1;" : "=f"(y) : "f"(x));
    return y;
}

// ================= fp32 -> bf16 hi/lo split =================
__global__ void split_f32(const float* __restrict__ x,
                          __nv_bfloat16* __restrict__ hi,
                          __nv_bfloat16* __restrict__ lo, int n4)
{
    int i = blockIdx.x * blockDim.x + threadIdx.x;
    if (i >= n4) return;
    float4 v = ((const float4*)x)[i];
    __nv_bfloat16 h0 = __float2bfloat16(v.x);
    __nv_bfloat16 h1 = __float2bfloat16(v.y);
    __nv_bfloat16 h2 = __float2bfloat16(v.z);
    __nv_bfloat16 h3 = __float2bfloat16(v.w);
    __nv_bfloat16 l0 = __float2bfloat16(v.x - __bfloat162float(h0));
    __nv_bfloat16 l1 = __float2bfloat16(v.y - __bfloat162float(h1));
    __nv_bfloat16 l2 = __float2bfloat16(v.z - __bfloat162float(h2));
    __nv_bfloat16 l3 = __float2bfloat16(v.w - __bfloat162float(h3));
    ((__nv_bfloat162*)hi)[2 * i]     = __nv_bfloat162(h0, h1);
    ((__nv_bfloat162*)hi)[2 * i + 1] = __nv_bfloat162(h2, h3);
    ((__nv_bfloat162*)lo)[2 * i]     = __nv_bfloat162(l0, l1);
    ((__nv_bfloat162*)lo)[2 * i + 1] = __nv_bfloat162(l2, l3);
}

// transpose + split: W [KDIM][Nw] fp32 -> hiT/loT [Nw][KDIM] bf16
__global__ void splitT(const float* __restrict__ W,
                       __nv_bfloat16* __restrict__ hiT,
                       __nv_bfloat16* __restrict__ loT, int Nw)
{
    __shared__ float t[32][33];
    int n0 = blockIdx.x * 32, k0 = blockIdx.y * 32;
    int tx = threadIdx.x, ty = threadIdx.y;
#pragma unroll
    for (int i = 0; i < 32; i += 8)
        t[ty + i][tx] = W[(size_t)(k0 + ty + i) * Nw + n0 + tx];
    __syncthreads();
#pragma unroll
    for (int i = 0; i < 32; i += 8) {
        float v = t[tx][ty + i];
        __nv_bfloat16 h = __float2bfloat16(v);
        size_t o = (size_t)(n0 + ty + i) * KDIM + k0 + tx;
        hiT[o] = h;
        loT[o] = __float2bfloat16(v - __bfloat162float(h));
    }
}

// ---------------- fused glue: rope-q + rope-k + v-split in one launch ----------
#define RQ_BLOCKS (MROWS * NHEADS * 64 / 256)       // 16384
#define RK_BLOCKS (MROWS * NKV * 64 / 256)          // 4096
#define VS_BLOCKS (MROWS * KVW / 4 / 256)           // 2048

__device__ __forceinline__ void rope_one(const float* __restrict__ x,
                                         __nv_bfloat16* __restrict__ hi,
                                         __nv_bfloat16* __restrict__ lo,
                                         int idx, int heads, float scale)
{
    int d = idx & 63;
    int t = idx >> 6;
    int h = t % heads;
    int m = t / heads;
    int s = m & (SEQ - 1);

    float e = -(float)d * (13.287712379549449f / 64.0f);
    float inv = exp2f(e);
    float ang = (float)s * inv;
    float sn, cs;
    sincosf(ang, &sn, &cs);

    size_t base = (size_t)m * (heads * 128) + h * 128 + d;
    float xlo = x[base];
    float xhi = x[base + 64];
    float y0 = (xlo * cs - xhi * sn) * scale;
    float y1 = (xhi * cs + xlo * sn) * scale;

    __nv_bfloat16 h0 = __float2bfloat16(y0);
    __nv_bfloat16 h1 = __float2bfloat16(y1);
    hi[base]      = h0;
    hi[base + 64] = h1;
    lo[base]      = __float2bfloat16(y0 - __bfloat162float(h0));
    lo[base + 64] = __float2bfloat16(y1 - __bfloat162float(h1));
}

__global__ void glue_kernel(const float* __restrict__ q,
                            const float* __restrict__ k,
                            const float* __restrict__ v,
                            __nv_bfloat16* __restrict__ qhi, __nv_bfloat16* __restrict__ qlo,
                            __nv_bfloat16* __restrict__ khi, __nv_bfloat16* __restrict__ klo,
                            __nv_bfloat16* __restrict__ vhi, __nv_bfloat16* __restrict__ vlo)
{
    int bx = blockIdx.x;
    if (bx < RQ_BLOCKS) {
        rope_one(q, qhi, qlo, bx * 256 + threadIdx.x, NHEADS, QSCALE_L2E);
    } else if (bx < RQ_BLOCKS + RK_BLOCKS) {
        rope_one(k, khi, klo, (bx - RQ_BLOCKS) * 256 + threadIdx.x, NKV, 1.0f);
    } else {
        int i = (bx - RQ_BLOCKS - RK_BLOCKS) * 256 + threadIdx.x;
        float4 vv = ((const float4*)v)[i];
        __nv_bfloat16 h0 = __float2bfloat16(vv.x);
        __nv_bfloat16 h1 = __float2bfloat16(vv.y);
        __nv_bfloat16 h2 = __float2bfloat16(vv.z);
        __nv_bfloat16 h3 = __float2bfloat16(vv.w);
        ((__nv_bfloat162*)vhi)[2 * i]     = __nv_bfloat162(h0, h1);
        ((__nv_bfloat162*)vhi)[2 * i + 1] = __nv_bfloat162(h2, h3);
        ((__nv_bfloat162*)vlo)[2 * i]     = __nv_bfloat162(
            __float2bfloat16(vv.x - __bfloat162float(h0)),
            __float2bfloat16(vv.y - __bfloat162float(h1)));
        ((__nv_bfloat162*)vlo)[2 * i + 1] = __nv_bfloat162(
            __float2bfloat16(vv.z - __bfloat162float(h2)),
            __float2bfloat16(vv.w - __bfloat162float(h3)));
    }
}

// ================= tensor-core GEMM via mma.sync, bf16x3 split =================
// Up to 3 fused (B, C) problem sets along blockIdx.x (range-selected).
#define BK 32
#define APITCH_B 80
#define TILE_B (128 * APITCH_B)
#define BUF_B (4 * TILE_B)
#define GSMEM (2 * BUF_B)
#define NCHG (KDIM / BK)

struct GemmProb {
    const __nv_bfloat16* Bhi;
    const __nv_bfloat16* Blo;
    float* C;
    int N;
};

__global__ __launch_bounds__(256, 2)
void gemm_mma(const __nv_bfloat16* __restrict__ Ahi,
              const __nv_bfloat16* __restrict__ Alo,
              GemmProb p0, GemmProb p1, GemmProb p2, int c0, int c1)
{
    extern __shared__ char smem[];
    const uint32_t sb = smem_u32(smem);
    const int tid = threadIdx.x;
    const int wid = tid >> 5, lane = tid & 31;
    const int wm = wid >> 2, wn = wid & 3;
    const int m0 = blockIdx.y << 7;

    int bx = blockIdx.x;
    const GemmProb* p;
    if (bx < c0)       { p = &p0; }
    else if (bx < c1)  { p = &p1; bx -= c0; }
    else               { p = &p2; bx -= c1; }
    const int n0 = bx << 7;
    const __nv_bfloat16* Bhi = p->Bhi;
    const __nv_bfloat16* Blo = p->Blo;
    float* C = p->C;
    const int N = p->N;

    const char* gsrc[4];
    gsrc[0] = (const char*)(Ahi + (size_t)m0 * KDIM);
    gsrc[1] = (const char*)(Alo + (size_t)m0 * KDIM);
    gsrc[2] = (const char*)(Bhi + (size_t)n0 * KDIM);
    gsrc[3] = (const char*)(Blo + (size_t)n0 * KDIM);

    const int r0 = tid >> 2, s0 = tid & 3;
    const int r1 = (tid + 256) >> 2, s1 = tid & 3;

    auto load_chunk = [&](int c) {
        const int buf = c & 1;
#pragma unroll
        for (int t = 0; t < 4; t++) {
            const char* gb = gsrc[t] + (size_t)c * (BK * 2);
            uint32_t st = sb + buf * BUF_B + t * TILE_B;
            CP_ASYNC16(st + r0 * APITCH_B + s0 * 16,
                       gb + (size_t)r0 * (KDIM * 2) + s0 * 16);
            CP_ASYNC16(st + r1 * APITCH_B + s1 * 16,
                       gb + (size_t)r1 * (KDIM * 2) + s1 * 16);
        }
    };

    float acc[4][4][4];
#pragma unroll
    for (int i = 0; i < 4; i++)
#pragma unroll
        for (int j = 0; j < 4; j++)
#pragma unroll
            for (int e = 0; e < 4; e++) acc[i][j][e] = 0.0f;

    const uint32_t a_off = (uint32_t)((lane & 15) * APITCH_B + (lane >> 4) * 16);
    const int bg = lane >> 3;
    const uint32_t b_off = (uint32_t)(((bg >> 1) * 8 + (lane & 7)) * APITCH_B + (bg & 1) * 16);

    load_chunk(0);
    CP_COMMIT();

    for (int c = 0; c < NCHG; ++c) {
        if (c + 1 < NCHG) load_chunk(c + 1);
        CP_COMMIT();
        CP_WAIT1();
        __syncthreads();

        const uint32_t base = sb + (c & 1) * BUF_B;
        const uint32_t sAhi = base + 0 * TILE_B + (wm * 64) * APITCH_B;
        const uint32_t sAlo = base + 1 * TILE_B + (wm * 64) * APITCH_B;
        const uint32_t sBhi = base + 2 * TILE_B + (wn * 32) * APITCH_B;
        const uint32_t sBlo = base + 3 * TILE_B + (wn * 32) * APITCH_B;
#pragma unroll
        for (int ks = 0; ks < 2; ks++) {
            const uint32_t koff = ks * 32;
            uint32_t ahi[4][4], bh[4][2];
#pragma unroll
            for (int fm = 0; fm < 4; fm++)
                ldsm_x4(ahi[fm], sAhi + fm * 16 * APITCH_B + koff + a_off);
#pragma unroll
            for (int f2 = 0; f2 < 2; f2++) {
                uint32_t r[4];
                ldsm_x4(r, sBhi + f2 * 16 * APITCH_B + koff + b_off);
                bh[2 * f2][0] = r[0]; bh[2 * f2][1] = r[1];
                bh[2 * f2 + 1][0] = r[2]; bh[2 * f2 + 1][1] = r[3];
            }
            // ahi x bhi
#pragma unroll
            for (int fm = 0; fm < 4; fm++)
#pragma unroll
                for (int fn = 0; fn < 4; fn++)
                    mma16816(acc[fm][fn], ahi[fm], bh[fn]);
            {
                uint32_t bl[4][2];
#pragma unroll
                for (int f2 = 0; f2 < 2; f2++) {
                    uint32_t r[4];
                    ldsm_x4(r, sBlo + f2 * 16 * APITCH_B + koff + b_off);
                    bl[2 * f2][0] = r[0]; bl[2 * f2][1] = r[1];
                    bl[2 * f2 + 1][0] = r[2]; bl[2 * f2 + 1][1] = r[3];
                }
                // ahi x blo
#pragma unroll
                for (int fm = 0; fm < 4; fm++)
#pragma unroll
                    for (int fn = 0; fn < 4; fn++)
                        mma16816(acc[fm][fn], ahi[fm], bl[fn]);
            }
            // alo x bhi (ahi registers dead; reuse)
            uint32_t alo[4][4];
#pragma unroll
            for (int fm = 0; fm < 4; fm++)
                ldsm_x4(alo[fm], sAlo + fm * 16 * APITCH_B + koff + a_off);
#pragma unroll
            for (int fm = 0; fm < 4; fm++)
#pragma unroll
                for (int fn = 0; fn < 4; fn++)
                    mma16816(acc[fm][fn], alo[fm], bh[fn]);
        }
        __syncthreads();
    }

    const int erow = lane >> 2;
    const int ecol = (lane & 3) * 2;
#pragma unroll
    for (int fm = 0; fm < 4; fm++) {
#pragma unroll
        for (int fn = 0; fn < 4; fn++) {
            int row = m0 + wm * 64 + fm * 16 + erow;
            int col = n0 + wn * 32 + fn * 8 + ecol;
            *(float2*)(C + (size_t)row * N + col) =
                make_float2(acc[fm][fn][0], acc[fm][fn][1]);
            *(float2*)(C + (size_t)(row + 8) * N + col) =
                make_float2(acc[fm][fn][2], acc[fm][fn][3]);
        }
    }
}

// ================= tensor-core flash attention (causal, GQA) =================
#define FPB 272                         // smem row pitch bytes (136 bf16)
#define QTILE_B (128 * FPB)             // 34816
#define KVTILE_B (64 * FPB)             // 17408
#define SMB_QHI 0
#define SMB_QLO QTILE_B
#define SMB_KV  (2 * QTILE_B)           // 8 kv tiles follow (2 bufs x 4)
#define FLASH_SMEM_B (2 * QTILE_B + 8 * KVTILE_B)  // 208896

__global__ __launch_bounds__(256, 1)
void flash_mma(const __nv_bfloat16* __restrict__ Qhi,
               const __nv_bfloat16* __restrict__ Qlo,
               const __nv_bfloat16* __restrict__ Khi,
               const __nv_bfloat16* __restrict__ Klo,
               const __nv_bfloat16* __restrict__ Vhi,
               const __nv_bfloat16* __restrict__ Vlo,
               __nv_bfloat16* __restrict__ Ohi,
               __nv_bfloat16* __restrict__ Olo)
{
    extern __shared__ char smem[];
    const uint32_t sb = smem_u32(smem);
    const int tid = threadIdx.x;
    const int wid = tid >> 5, lane = tid & 31;
    const int qt = 15 - (int)blockIdx.x;     // heavy tiles first
    const int h = blockIdx.y, b = blockIdx.z;
    const int g = h >> 2;
    const int q0 = qt << 7;
    const int ntiles = 2 * qt + 2;           // 64-col kv tiles

    const uint32_t a_off = (uint32_t)((lane & 15) * FPB + (lane >> 4) * 16);

    const char* kh_base = (const char*)(Khi + (size_t)(b * SEQ) * KVW + g * HD);
    const char* kl_base = (const char*)(Klo + (size_t)(b * SEQ) * KVW + g * HD);
    const char* vh_base = (const char*)(Vhi + (size_t)(b * SEQ) * KVW + g * HD);
    const char* vl_base = (const char*)(Vlo + (size_t)(b * SEQ) * KVW + g * HD);

    auto issue_kv = [&](int j) {
        const uint32_t dst = sb + SMB_KV + (j & 1) * (4 * KVTILE_B);
        const int k0 = j << 6;
        const char* srcs[4] = {kh_base, kl_base, vh_base, vl_base};
#pragma unroll
        for (int t = 0; t < 4; t++) {
#pragma unroll
            for (int i = 0; i < 4; i++) {
                int idx = i * 256 + tid;         // 0..1023
                int row = idx >> 4, c = idx & 15;
                CP_ASYNC16(dst + t * KVTILE_B + row * FPB + c * 16,
                           srcs[t] + (size_t)(k0 + row) * (KVW * 2) + c * 16);
            }
        }
    };

    // ---- prologue: Q tiles + first two KV tiles ----
    {
        const char* qh = (const char*)(Qhi + (size_t)(b * SEQ + q0) * HIDDEN + h * HD);
        const char* ql = (const char*)(Qlo + (size_t)(b * SEQ + q0) * HIDDEN + h * HD);
#pragma unroll
        for (int i = 0; i < 8; i++) {
            int idx = i * 256 + tid;
            int row = idx >> 4, c = idx & 15;
            CP_ASYNC16(sb + SMB_QHI + row * FPB + c * 16,
                       qh + (size_t)row * (HIDDEN * 2) + c * 16);
            CP_ASYNC16(sb + SMB_QLO + row * FPB + c * 16,
                       ql + (size_t)row * (HIDDEN * 2) + c * 16);
        }
        CP_COMMIT();
    }
    issue_kv(0);
    CP_COMMIT();
    issue_kv(1);   // ntiles >= 2 always
    CP_COMMIT();

    float o[16][4];
#pragma unroll
    for (int nt = 0; nt < 16; nt++)
#pragma unroll
        for (int e = 0; e < 4; e++) o[nt][e] = 0.0f;
    float mrow0 = -INFINITY, mrow1 = -INFINITY, lrow0 = 0.0f, lrow1 = 0.0f;

    for (int j = 0; j < ntiles; j++) {
        if (j + 1 < ntiles) { CP_WAIT1(); } else { CP_WAIT0(); }
        __syncthreads();

        const uint32_t kvb = sb + SMB_KV + (j & 1) * (4 * KVTILE_B);
        const uint32_t skhi = kvb;
        const uint32_t sklo = kvb + KVTILE_B;
        const uint32_t svhi = kvb + 2 * KVTILE_B;
        const uint32_t svlo = kvb + 3 * KVTILE_B;
        const int k0 = j << 6;

        // ---- S = Q . K^T (3 passes hi/lo), 128 q-rows x 64 k-cols ----
        float s[8][4];
#pragma unroll
        for (int nt = 0; nt < 8; nt++)
#pragma unroll
            for (int e = 0; e < 4; e++) s[nt][e] = 0.0f;

#pragma unroll
        for (int ks = 0; ks < 8; ks++) {
            uint32_t ahi[4], alo[4];
            ldsm_x4(ahi, sb + SMB_QHI + (wid * 16) * FPB + ks * 32 + a_off);
            ldsm_x4(alo, sb + SMB_QLO + (wid * 16) * FPB + ks * 32 + a_off);
#pragma unroll
            for (int nt2 = 0; nt2 < 4; nt2++) {
                uint32_t kh[4], kl[4];
                ldsm_x4(kh, skhi + (nt2 * 16) * FPB + ks * 32 + a_off);
                ldsm_x4(kl, sklo + (nt2 * 16) * FPB + ks * 32 + a_off);
                uint32_t bh0[2] = {kh[0], kh[2]}, bh1[2] = {kh[1], kh[3]};
                uint32_t bl0[2] = {kl[0], kl[2]}, bl1[2] = {kl[1], kl[3]};
                mma16816(s[2 * nt2],     ahi, bh0);
                mma16816(s[2 * nt2 + 1], ahi, bh1);
                mma16816(s[2 * nt2],     ahi, bl0);
                mma16816(s[2 * nt2 + 1], ahi, bl1);
                mma16816(s[2 * nt2],     alo, bh0);
                mma16816(s[2 * nt2 + 1], alo, bh1);
            }
        }

        // ---- causal mask (diagonal block tiles) ----
        if (k0 + 64 > q0) {
            const int rq = q0 + wid * 16 + (lane >> 2) - k0;
            const int lc = 2 * (lane & 3);
#pragma unroll
            for (int nt = 0; nt < 8; nt++) {
                int ln = nt * 8 + lc;
                if (ln > rq)         s[nt][0] = -1e30f;
                if (ln + 1 > rq)     s[nt][1] = -1e30f;
                if (ln > rq + 8)     s[nt][2] = -1e30f;
                if (ln + 1 > rq + 8) s[nt][3] = -1e30f;
            }
        }

        // ---- online softmax (log2-domain; Q pre-scaled by log2e/sqrt(d)) ----
        float mx0 = -1e30f, mx1 = -1e30f;
#pragma unroll
        for (int nt = 0; nt < 8; nt++) {
            mx0 = fmaxf(mx0, fmaxf(s[nt][0], s[nt][1]));
            mx1 = fmaxf(mx1, fmaxf(s[nt][2], s[nt][3]));
        }
        mx0 = fmaxf(mx0, __shfl_xor_sync(0xffffffffu, mx0, 1));
        mx0 = fmaxf(mx0, __shfl_xor_sync(0xffffffffu, mx0, 2));
        mx1 = fmaxf(mx1, __shfl_xor_sync(0xffffffffu, mx1, 1));
        mx1 = fmaxf(mx1, __shfl_xor_sync(0xffffffffu, mx1, 2));
        const float newm0 = fmaxf(mrow0, mx0);
        const float newm1 = fmaxf(mrow1, mx1);

        float rs0 = 0.0f, rs1 = 0.0f;
#pragma unroll
        for (int nt = 0; nt < 8; nt++) {
            s[nt][0] = fexp2(s[nt][0] - newm0);
            s[nt][1] = fexp2(s[nt][1] - newm0);
            s[nt][2] = fexp2(s[nt][2] - newm1);
            s[nt][3] = fexp2(s[nt][3] - newm1);
            rs0 += s[nt][0] + s[nt][1];
            rs1 += s[nt][2] + s[nt][3];
        }
        rs0 += __shfl_xor_sync(0xffffffffu, rs0, 1);
        rs0 += __shfl_xor_sync(0xffffffffu, rs0, 2);
        rs1 += __shfl_xor_sync(0xffffffffu, rs1, 1);
        rs1 += __shfl_xor_sync(0xffffffffu, rs1, 2);

        const float al0 = fexp2(mrow0 - newm0);
        const float al1 = fexp2(mrow1 - newm1);
        lrow0 = lrow0 * al0 + rs0;
        lrow1 = lrow1 * al1 + rs1;
        mrow0 = newm0;
        mrow1 = newm1;
#pragma unroll
        for (int nt = 0; nt < 16; nt++) {
            o[nt][0] *= al0; o[nt][1] *= al0;
            o[nt][2] *= al1; o[nt][3] *= al1;
        }

        // ---- O += P . V  (P hi/lo in registers, V hi/lo in smem; 3 passes) ----
#pragma unroll
        for (int t = 0; t < 4; t++) {
            float p00 = s[2 * t][0], p01 = s[2 * t][1];
            float p02 = s[2 * t][2], p03 = s[2 * t][3];
            float p10 = s[2 * t + 1][0], p11 = s[2 * t + 1][1];
            float p12 = s[2 * t + 1][2], p13 = s[2 * t + 1][3];
            uint32_t aph[4], apl[4];
            aph[0] = packbf(p00, p01);
            aph[1] = packbf(p02, p03);
            aph[2] = packbf(p10, p11);
            aph[3] = packbf(p12, p13);
            {
                __nv_bfloat162* hp;
                hp = (__nv_bfloat162*)&aph[0];
                apl[0] = packbf(p00 - __bfloat162float(hp->x), p01 - __bfloat162float(hp->y));
                hp = (__nv_bfloat162*)&aph[1];
                apl[1] = packbf(p02 - __bfloat162float(hp->x), p03 - __bfloat162float(hp->y));
                hp = (__nv_bfloat162*)&aph[2];
                apl[2] = packbf(p10 - __bfloat162float(hp->x), p11 - __bfloat162float(hp->y));
                hp = (__nv_bfloat162*)&aph[3];
                apl[3] = packbf(p12 - __bfloat162float(hp->x), p13 - __bfloat162float(hp->y));
            }
#pragma unroll
            for (int nt2 = 0; nt2 < 8; nt2++) {
                uint32_t vh[4], vl[4];
                ldsm_x4_t(vh, svhi + (t * 16) * FPB + nt2 * 32 + a_off);
                ldsm_x4_t(vl, svlo + (t * 16) * FPB + nt2 * 32 + a_off);
                uint32_t bh0[2] = {vh[0], vh[1]}, bh1[2] = {vh[2], vh[3]};
                uint32_t bl0[2] = {vl[0], vl[1]}, bl1[2] = {vl[2], vl[3]};
                mma16816(o[2 * nt2],     aph, bh0);
                mma16816(o[2 * nt2 + 1], aph, bh1);
                mma16816(o[2 * nt2],     aph, bl0);
                mma16816(o[2 * nt2 + 1], aph, bl1);
                mma16816(o[2 * nt2],     apl, bh0);
                mma16816(o[2 * nt2 + 1], apl, bh1);
            }
        }

        __syncthreads();               // done reading buffer (j & 1)
        if (j + 2 < ntiles) {
            issue_kv(j + 2);
            CP_COMMIT();
        }
    }

    // ---- epilogue: normalize, split to hi/lo bf16, write ----
    const float invl0 = 1.0f / lrow0;
    const float invl1 = 1.0f / lrow1;
    const int grow = b * SEQ + q0 + wid * 16 + (lane >> 2);
    const size_t cbase = (size_t)grow * HIDDEN + h * HD + 2 * (lane & 3);
#pragma unroll
    for (int nt = 0; nt < 16; nt++) {
        float v0 = o[nt][0] * invl0, v1 = o[nt][1] * invl0;
        float v2 = o[nt][2] * invl1, v3 = o[nt][3] * invl1;
        uint32_t h01 = packbf(v0, v1);
        uint32_t h23 = packbf(v2, v3);
        __nv_bfloat162* hp01 = (__nv_bfloat162*)&h01;
        __nv_bfloat162* hp23 = (__nv_bfloat162*)&h23;
        uint32_t l01 = packbf(v0 - __bfloat162float(hp01->x),
                              v1 - __bfloat162float(hp01->y));
        uint32_t l23 = packbf(v2 - __bfloat162float(hp23->x),
                              v3 - __bfloat162float(hp23->y));
        *(uint32_t*)(Ohi + cbase + nt * 8) = h01;
        *(uint32_t*)(Olo + cbase + nt * 8) = l01;
        *(uint32_t*)(Ohi + cbase + (size_t)8 * HIDDEN + nt * 8) = h23;
        *(uint32_t*)(Olo + cbase + (size_t)8 * HIDDEN + nt * 8) = l23;
    }
}

// ---------------- launch ----------------
extern "C" void kernel_launch(void* const* d_in, const int* in_sizes, int n_in,
                              void* d_out, int out_size)
{
    const float* x  = (const float*)d_in[0];
    const float* wq = (const float*)d_in[1];
    const float* wk = (const float*)d_in[2];
    const float* wv = (const float*)d_in[3];
    const float* wo = (const float*)d_in[4];
    float* out = (float*)d_out;

    float *qp, *kp, *vp;
    cudaGetSymbolAddress((void**)&qp, g_q);
    cudaGetSymbolAddress((void**)&kp, g_k);
    cudaGetSymbolAddress((void**)&vp, g_v);
    __nv_bfloat16 *xhi, *xlo, *ahi, *alo, *khi, *klo, *vhi, *vlo;
    __nv_bfloat16 *wqhi, *wqlo, *wkhi, *wklo, *wvhi, *wvlo, *wohi, *wolo;
    cudaGetSymbolAddress((void**)&xhi, g_xhi);
    cudaGetSymbolAddress((void**)&xlo, g_xlo);
    cudaGetSymbolAddress((void**)&ahi, g_ahi);
    cudaGetSymbolAddress((void**)&alo, g_alo);
    cudaGetSymbolAddress((void**)&khi, g_khi);
    cudaGetSymbolAddress((void**)&klo, g_klo);
    cudaGetSymbolAddress((void**)&vhi, g_vhi);
    cudaGetSymbolAddress((void**)&vlo, g_vlo);
    cudaGetSymbolAddress((void**)&wqhi, g_wqhi);
    cudaGetSymbolAddress((void**)&wqlo, g_wqlo);
    cudaGetSymbolAddress((void**)&wkhi, g_wkhi);
    cudaGetSymbolAddress((void**)&wklo, g_wklo);
    cudaGetSymbolAddress((void**)&wvhi, g_wvhi);
    cudaGetSymbolAddress((void**)&wvlo, g_wvlo);
    cudaGetSymbolAddress((void**)&wohi, g_wohi);
    cudaGetSymbolAddress((void**)&wolo, g_wolo);

    cudaFuncSetAttribute(gemm_mma,
                         cudaFuncAttributeMaxDynamicSharedMemorySize, GSMEM);
    cudaFuncSetAttribute(flash_mma,
                         cudaFuncAttributeMaxDynamicSharedMemorySize, FLASH_SMEM_B);

    const int n4x = MROWS * KDIM / 4;

    GemmProb pq = {wqhi, wqlo, qp, HIDDEN};
    GemmProb pk = {wkhi, wklo, kp, KVW};
    GemmProb pv = {wvhi, wvlo, vp, KVW};
    GemmProb po = {wohi, wolo, out, HIDDEN};

    // launches 1-4: input split + Q/K/V weight splits
    split_f32<<<(n4x + 255) / 256, 256>>>(x, xhi, xlo, n4x);
    splitT<<<dim3(HIDDEN / 32, KDIM / 32), dim3(32, 8)>>>(wq, wqhi, wqlo, HIDDEN);
    splitT<<<dim3(KVW / 32, KDIM / 32), dim3(32, 8)>>>(wk, wkhi, wklo, KVW);
    splitT<<<dim3(KVW / 32, KDIM / 32), dim3(32, 8)>>>(wv, wvhi, wvlo, KVW);

    // launch 5 (ncu-profiled): fused Q+K+V projection, grid.x = 16 + 4 + 4
    gemm_mma<<<dim3(24, MROWS / 128), 256, GSMEM>>>(xhi, xlo, pq, pk, pv, 16, 20);

    // launch 6: fused glue (rope-q + rope-k + v-split)
    glue_kernel<<<RQ_BLOCKS + RK_BLOCKS + VS_BLOCKS, 256>>>(
        qp, kp, vp, xhi, xlo, khi, klo, vhi, vlo);

    // launch 7: causal flash attention (writes att hi/lo directly)
    flash_mma<<<dim3(SEQ / 128, NHEADS, BATCH), 256, FLASH_SMEM_B>>>(
        xhi, xlo, khi, klo, vhi, vlo, ahi, alo);

    // launch 8: wo split (deferred — only needed before O projection)
    splitT<<<dim3(HIDDEN / 32, KDIM / 32), dim3(32, 8)>>>(wo, wohi, wolo, HIDDEN);

    // launch 9: output projection
    gemm_mma<<<dim3(16, MROWS / 128), 256, GSMEM>>>(ahi, alo, po, po, po, 16, 16);
}